// round 5
// baseline (speedup 1.0000x reference)
#include <cuda_runtime.h>
#include <math.h>

// ---------------- Problem constants ----------------
#define S      4096
#define HID    2048
#define NH     16
#define NKV    4
#define DD     128
#define FF     768
#define EPSV   1e-8f

#define OUT_ELEMS    (S * HID)            // 8388608
#define MEM_ELEMS    (NH * FF * DD)       // 1572864
#define NORM_ELEMS   (NH * FF)            // 12288

// ---------------- Scratch (device globals; no allocation allowed) ----------------
__device__ __align__(16) float g_K  [S * 512];
__device__ __align__(16) float g_V  [S * 512];
__device__ __align__(16) float g_Q  [S * HID];
__device__ __align__(16) float g_MB [S * HID];
__device__ __align__(16) float g_G  [S * HID];
__device__ __align__(16) float g_MK [(size_t)NKV * S * FF];
__device__ __align__(16) float g_MQ [(size_t)NH * S * FF];
__device__ __align__(16) float g_NUM[(size_t)NH * S * DD];   // reused: num, then num_a
__device__ __align__(16) float g_WMV[(size_t)NH * S * DD];
__device__ __align__(16) float g_DELTA[4][(size_t)NH * FF * DD]; // split-K partials
__device__ float g_DEN [NH * S];
__device__ float g_COEF[NH * S];
__device__ float g_DENA[NH * S];

// ---------------- helpers ----------------
__device__ __forceinline__ float warp_sum(float v) {
#pragma unroll
    for (int o = 16; o > 0; o >>= 1) v += __shfl_down_sync(0xffffffffu, v, o);
    return v;
}

// ======================================================================
// SGEMM: C[M,N] = A[M,K] @ W[N,K]^T + bias, optional sigmoid.
// BM=BN=128, BK=8, 256 threads, 8x8 microtile.
// ======================================================================
template <int ACT>
__global__ __launch_bounds__(256) void sgemm_bias(
    const float* __restrict__ A, const float* __restrict__ W,
    const float* __restrict__ bias, float* __restrict__ C,
    int M, int N, int K)
{
    __shared__ float As[8][128];
    __shared__ float Ws[8][128];
    const int tid = threadIdx.x;
    const int bm = blockIdx.y * 128;
    const int bn = blockIdx.x * 128;
    const int lr = tid >> 1;
    const int lc = (tid & 1) * 4;
    const int ty = (tid >> 4) * 8;
    const int tx = (tid & 15) * 8;

    const float* Ap = A + (size_t)(bm + lr) * K + lc;
    const float* Wp = W + (size_t)(bn + lr) * K + lc;

    float acc[8][8];
#pragma unroll
    for (int i = 0; i < 8; i++)
#pragma unroll
        for (int j = 0; j < 8; j++) acc[i][j] = 0.f;

    for (int k0 = 0; k0 < K; k0 += 8) {
        float4 av = *(const float4*)(Ap + k0);
        float4 wv = *(const float4*)(Wp + k0);
        As[lc + 0][lr] = av.x; As[lc + 1][lr] = av.y;
        As[lc + 2][lr] = av.z; As[lc + 3][lr] = av.w;
        Ws[lc + 0][lr] = wv.x; Ws[lc + 1][lr] = wv.y;
        Ws[lc + 2][lr] = wv.z; Ws[lc + 3][lr] = wv.w;
        __syncthreads();
#pragma unroll
        for (int kk = 0; kk < 8; kk++) {
            float4 a0 = *(const float4*)(&As[kk][ty]);
            float4 a1 = *(const float4*)(&As[kk][ty + 4]);
            float4 b0 = *(const float4*)(&Ws[kk][tx]);
            float4 b1 = *(const float4*)(&Ws[kk][tx + 4]);
            float a[8] = {a0.x, a0.y, a0.z, a0.w, a1.x, a1.y, a1.z, a1.w};
            float b[8] = {b0.x, b0.y, b0.z, b0.w, b1.x, b1.y, b1.z, b1.w};
#pragma unroll
            for (int i = 0; i < 8; i++)
#pragma unroll
                for (int j = 0; j < 8; j++)
                    acc[i][j] = fmaf(a[i], b[j], acc[i][j]);
        }
        __syncthreads();
    }

    float bb[8];
#pragma unroll
    for (int j = 0; j < 8; j++) bb[j] = bias[bn + tx + j];

#pragma unroll
    for (int i = 0; i < 8; i++) {
        float v[8];
#pragma unroll
        for (int j = 0; j < 8; j++) {
            float t = acc[i][j] + bb[j];
            if (ACT) t = 1.f / (1.f + expf(-t));
            v[j] = t;
        }
        float* cp = C + (size_t)(bm + ty + i) * N + bn + tx;
        *(float4*)(cp)     = make_float4(v[0], v[1], v[2], v[3]);
        *(float4*)(cp + 4) = make_float4(v[4], v[5], v[6], v[7]);
    }
}

// ======================================================================
// Skinny GEMM: per head h, C[h][M,128] = A[h/adiv][M,K] @ B[h][K,128].
// A row-major (K contiguous), B row-major (128 contiguous).
// grid = (M/128, NH). Used for num (adiv=4, B=memory) and num_a (adiv=1, B=new_memory).
// ======================================================================
__global__ __launch_bounds__(256) void gemm_skinny(
    const float* __restrict__ Abase, int adiv, size_t a_stride,
    const float* __restrict__ Bbase, size_t b_stride,
    float* __restrict__ Cbase, size_t c_stride, int K)
{
    const int h = blockIdx.y;
    const float* A = Abase + (size_t)(h / adiv) * a_stride;
    const float* B = Bbase + (size_t)h * b_stride;
    float* C = Cbase + (size_t)h * c_stride;

    __shared__ float As[8][128];
    __shared__ float Bs[8][128];
    const int tid = threadIdx.x;
    const int bm = blockIdx.x * 128;
    const int alr = tid >> 1;
    const int alc = (tid & 1) * 4;
    const int bk  = tid >> 5;
    const int bn4 = (tid & 31) * 4;
    const int ty = (tid >> 4) * 8;
    const int tx = (tid & 15) * 8;

    const float* Ap = A + (size_t)(bm + alr) * K + alc;

    float acc[8][8];
#pragma unroll
    for (int i = 0; i < 8; i++)
#pragma unroll
        for (int j = 0; j < 8; j++) acc[i][j] = 0.f;

    for (int k0 = 0; k0 < K; k0 += 8) {
        float4 av = *(const float4*)(Ap + k0);
        float4 bv = *(const float4*)(B + (size_t)(k0 + bk) * 128 + bn4);
        As[alc + 0][alr] = av.x; As[alc + 1][alr] = av.y;
        As[alc + 2][alr] = av.z; As[alc + 3][alr] = av.w;
        *(float4*)(&Bs[bk][bn4]) = bv;
        __syncthreads();
#pragma unroll
        for (int kk = 0; kk < 8; kk++) {
            float4 a0 = *(const float4*)(&As[kk][ty]);
            float4 a1 = *(const float4*)(&As[kk][ty + 4]);
            float4 b0 = *(const float4*)(&Bs[kk][tx]);
            float4 b1 = *(const float4*)(&Bs[kk][tx + 4]);
            float a[8] = {a0.x, a0.y, a0.z, a0.w, a1.x, a1.y, a1.z, a1.w};
            float b[8] = {b0.x, b0.y, b0.z, b0.w, b1.x, b1.y, b1.z, b1.w};
#pragma unroll
            for (int i = 0; i < 8; i++)
#pragma unroll
                for (int j = 0; j < 8; j++)
                    acc[i][j] = fmaf(a[i], b[j], acc[i][j]);
        }
        __syncthreads();
    }

#pragma unroll
    for (int i = 0; i < 8; i++) {
        float* cp = C + (size_t)(bm + ty + i) * 128 + tx;
        *(float4*)(cp)     = make_float4(acc[i][0], acc[i][1], acc[i][2], acc[i][3]);
        *(float4*)(cp + 4) = make_float4(acc[i][4], acc[i][5], acc[i][6], acc[i][7]);
    }
}

// ======================================================================
// Delta GEMM (split-K): DELTA[part][h][f,d] = sum_{s in part} MK[h/4][s,f]*WMV[h][s,d]
// grid = (F/128=6, 4 parts, 16 heads). Both operands are [s][col] panels.
// ======================================================================
__global__ __launch_bounds__(256) void gemm_delta()
{
    const int h    = blockIdx.z;
    const int part = blockIdx.y;
    const int f0   = blockIdx.x * 128;
    const float* A = g_MK + (size_t)(h >> 2) * S * FF;   // [S][F]
    const float* B = g_WMV + (size_t)h * S * DD;         // [S][128]

    __shared__ float As[8][128];
    __shared__ float Bs[8][128];
    const int tid = threadIdx.x;
    const int k  = tid >> 5;
    const int c4 = (tid & 31) * 4;
    const int ty = (tid >> 4) * 8;
    const int tx = (tid & 15) * 8;

    float acc[8][8];
#pragma unroll
    for (int i = 0; i < 8; i++)
#pragma unroll
        for (int j = 0; j < 8; j++) acc[i][j] = 0.f;

    const int kbeg = part * (S / 4);
    const int kend = kbeg + (S / 4);
    for (int k0 = kbeg; k0 < kend; k0 += 8) {
        *(float4*)(&As[k][c4]) = *(const float4*)(A + (size_t)(k0 + k) * FF + f0 + c4);
        *(float4*)(&Bs[k][c4]) = *(const float4*)(B + (size_t)(k0 + k) * 128 + c4);
        __syncthreads();
#pragma unroll
        for (int kk = 0; kk < 8; kk++) {
            float4 a0 = *(const float4*)(&As[kk][ty]);
            float4 a1 = *(const float4*)(&As[kk][ty + 4]);
            float4 b0 = *(const float4*)(&Bs[kk][tx]);
            float4 b1 = *(const float4*)(&Bs[kk][tx + 4]);
            float a[8] = {a0.x, a0.y, a0.z, a0.w, a1.x, a1.y, a1.z, a1.w};
            float b[8] = {b0.x, b0.y, b0.z, b0.w, b1.x, b1.y, b1.z, b1.w};
#pragma unroll
            for (int i = 0; i < 8; i++)
#pragma unroll
                for (int j = 0; j < 8; j++)
                    acc[i][j] = fmaf(a[i], b[j], acc[i][j]);
        }
        __syncthreads();
    }

    float* Cp = g_DELTA[part] + (size_t)h * FF * DD;
#pragma unroll
    for (int i = 0; i < 8; i++) {
        float* cp = Cp + (size_t)(f0 + ty + i) * 128 + tx;
        *(float4*)(cp)     = make_float4(acc[i][0], acc[i][1], acc[i][2], acc[i][3]);
        *(float4*)(cp + 4) = make_float4(acc[i][4], acc[i][5], acc[i][6], acc[i][7]);
    }
}

// ======================================================================
// dpfp + L2-normalize. grid=(S, nheads). 256 threads.
// mk[j*256+i] = y[i]*y[(i-j-1) mod 256], j=0..2, y = [relu(x), relu(-x)].
// WITHDEN: also fuse denom[h,s] = dot(mk_norm, norm[h]) + EPS and coef.
// ======================================================================
template <bool WITHDEN>
__global__ __launch_bounds__(256) void dpfp_kernel(
    const float* __restrict__ X, float* __restrict__ mkout,
    const float* __restrict__ normv)
{
    const int s  = blockIdx.x;
    const int hh = blockIdx.y;
    const int nh = gridDim.y;
    const int t  = threadIdx.x;
    __shared__ float y[256];
    __shared__ float red[5][8];

    const float* x = X + ((size_t)s * nh + hh) * 128;
    float xv = (t < 128) ? x[t] : -x[t - 128];
    y[t] = fmaxf(xv, 0.f);
    __syncthreads();

    float yi = y[t];
    float m0 = yi * y[(t - 1) & 255];
    float m1 = yi * y[(t - 2) & 255];
    float m2 = yi * y[(t - 3) & 255];
    float ss = m0 * m0 + m1 * m1 + m2 * m2;

    float dd[4];
    if (WITHDEN) {
#pragma unroll
        for (int g = 0; g < 4; g++) {
            const float* nr = normv + (size_t)(4 * hh + g) * FF;
            dd[g] = m0 * nr[t] + m1 * nr[256 + t] + m2 * nr[512 + t];
        }
    }

    const int lane = t & 31, w = t >> 5;
    float r0 = warp_sum(ss);
    if (lane == 0) red[0][w] = r0;
    if (WITHDEN) {
#pragma unroll
        for (int g = 0; g < 4; g++) {
            float rg = warp_sum(dd[g]);
            if (lane == 0) red[1 + g][w] = rg;
        }
    }
    __syncthreads();

    float ssT = 0.f;
#pragma unroll
    for (int w2 = 0; w2 < 8; w2++) ssT += red[0][w2];
    float nrm = sqrtf(ssT);
    float inv = 1.f / fmaxf(nrm, 1e-12f);

    float* o = mkout + ((size_t)hh * S + s) * FF;
    o[t]       = m0 * inv;
    o[256 + t] = m1 * inv;
    o[512 + t] = m2 * inv;

    if (WITHDEN && t < 4) {
        float dT = 0.f;
#pragma unroll
        for (int w2 = 0; w2 < 8; w2++) dT += red[1 + t][w2];
        float den  = dT * inv + EPSV;
        float mksq = ssT * inv * inv;
        float coef = 1.f - den / mksq;
        coef = fminf(fmaxf(coef, 0.f), 1.f);
        int h = 4 * hh + t;
        g_DEN[h * S + s]  = den;
        g_COEF[h * S + s] = coef;
    }
}

// ======================================================================
// weighted_mv = (v - num/denom) * mb. NH*S*D elements.
// ======================================================================
__global__ void wmv_kernel()
{
    size_t idx = (size_t)blockIdx.x * 256 + threadIdx.x;
    int h = (int)(idx >> 19);             // S*D = 2^19
    size_t r = idx & ((1u << 19) - 1);
    int s  = (int)(r >> 7);
    int d0 = (int)(r & 127);
    float den  = g_DEN[h * S + s];
    float prev = g_NUM[idx] / den;
    float v  = g_V[(size_t)s * 512 + (size_t)(h >> 2) * 128 + d0];
    float mb = g_MB[(size_t)s * HID + (size_t)h * 128 + d0];
    g_WMV[idx] = (v - prev) * mb;
}

// ======================================================================
// new_norm[h][f] = norm[h][f] + sum_s coef[h][s]*MK[h/4][s][f]
// grid = (F/64=12, NKV). 256 threads: 64 f-lanes x 4 s-lanes.
// ======================================================================
__global__ __launch_bounds__(256) void delta_norm_kernel(
    const float* __restrict__ normv, float* __restrict__ out_norm)
{
    const int kv = blockIdx.y;
    const int f0 = blockIdx.x * 64;
    const int t  = threadIdx.x;
    const int fl = t & 63, sl = t >> 6;

    float acc[4] = {0.f, 0.f, 0.f, 0.f};
    const float* mkbase = g_MK + (size_t)kv * S * FF + f0 + fl;
    for (int s = sl; s < S; s += 4) {
        float v = mkbase[(size_t)s * FF];
#pragma unroll
        for (int g = 0; g < 4; g++)
            acc[g] = fmaf(g_COEF[(4 * kv + g) * S + s], v, acc[g]);
    }
    __shared__ float sm[4][4][64];
#pragma unroll
    for (int g = 0; g < 4; g++) sm[sl][g][fl] = acc[g];
    __syncthreads();
    if (t < 64) {
#pragma unroll
        for (int g = 0; g < 4; g++) {
            float sum = sm[0][g][t] + sm[1][g][t] + sm[2][g][t] + sm[3][g][t];
            int h = 4 * kv + g;
            out_norm[(size_t)h * FF + f0 + t] = normv[(size_t)h * FF + f0 + t] + sum;
        }
    }
}

// new_memory = memory + sum of split-K partials
__global__ void add_delta_kernel(const float* __restrict__ memory,
                                 float* __restrict__ out_mem)
{
    size_t idx = (size_t)blockIdx.x * 256 + threadIdx.x;
    out_mem[idx] = memory[idx] + g_DELTA[0][idx] + g_DELTA[1][idx]
                 + g_DELTA[2][idx] + g_DELTA[3][idx];
}

// den_a[h,s] = dot(mq[h,s], new_norm[h]) + EPS. grid=(S,NH).
__global__ __launch_bounds__(256) void dena_kernel(const float* __restrict__ newnorm)
{
    const int s = blockIdx.x, h = blockIdx.y;
    const int t = threadIdx.x;
    const float* mq = g_MQ + ((size_t)h * S + s) * FF;
    const float* nr = newnorm + (size_t)h * FF;
    float dd = mq[t] * nr[t] + mq[256 + t] * nr[256 + t] + mq[512 + t] * nr[512 + t];
    __shared__ float red[8];
    float r = warp_sum(dd);
    if ((t & 31) == 0) red[t >> 5] = r;
    __syncthreads();
    if (t == 0) {
        float s8 = 0.f;
#pragma unroll
        for (int w = 0; w < 8; w++) s8 += red[w];
        g_DENA[h * S + s] = s8 + EPSV;
    }
}

// out = hidden + gate * (num_a / den_a) with [B,H,S,D]->[S,HID] transpose
__global__ void final_kernel(const float* __restrict__ X, float* __restrict__ out)
{
    size_t idx = (size_t)blockIdx.x * 256 + threadIdx.x;
    int s  = (int)(idx >> 11);
    int c  = (int)(idx & 2047);
    int h  = c >> 7;
    int d0 = c & 127;
    float numa = g_NUM[((size_t)h * S + s) * DD + d0];
    float mh = numa / g_DENA[h * S + s];
    out[idx] = X[idx] + g_G[idx] * mh;
}

// ======================================================================
// Launch
// ======================================================================
extern "C" void kernel_launch(void* const* d_in, const int* in_sizes, int n_in,
                              void* d_out, int out_size)
{
    const float* X    = (const float*)d_in[0];
    const float* Wq   = (const float*)d_in[1];
    const float* bq   = (const float*)d_in[2];
    const float* Wk   = (const float*)d_in[3];
    const float* bk   = (const float*)d_in[4];
    const float* Wv   = (const float*)d_in[5];
    const float* bv   = (const float*)d_in[6];
    const float* Wg   = (const float*)d_in[7];
    const float* bg   = (const float*)d_in[8];
    const float* Wmb  = (const float*)d_in[9];
    const float* bmb  = (const float*)d_in[10];
    const float* memv = (const float*)d_in[11];
    const float* normv= (const float*)d_in[12];

    float* out      = (float*)d_out;
    float* out_mem  = out + OUT_ELEMS;
    float* out_norm = out_mem + MEM_ELEMS;

    float *pK, *pV, *pQ, *pMB, *pG, *pMK, *pMQ, *pNUM;
    cudaGetSymbolAddress((void**)&pK,  g_K);
    cudaGetSymbolAddress((void**)&pV,  g_V);
    cudaGetSymbolAddress((void**)&pQ,  g_Q);
    cudaGetSymbolAddress((void**)&pMB, g_MB);
    cudaGetSymbolAddress((void**)&pG,  g_G);
    cudaGetSymbolAddress((void**)&pMK, g_MK);
    cudaGetSymbolAddress((void**)&pMQ, g_MQ);
    cudaGetSymbolAddress((void**)&pNUM, g_NUM);

    dim3 blk(256);

    // 1) Projections
    sgemm_bias<0><<<dim3(HID / 128, S / 128), blk>>>(X, Wq,  bq,  pQ,  S, HID, HID);
    sgemm_bias<0><<<dim3(512 / 128, S / 128), blk>>>(X, Wk,  bk,  pK,  S, 512, HID);
    sgemm_bias<0><<<dim3(512 / 128, S / 128), blk>>>(X, Wv,  bv,  pV,  S, 512, HID);
    sgemm_bias<1><<<dim3(HID / 128, S / 128), blk>>>(X, Wmb, bmb, pMB, S, HID, HID);
    sgemm_bias<1><<<dim3(HID / 128, S / 128), blk>>>(X, Wg,  bg,  pG,  S, HID, HID);

    // 2) dpfp + normalize (K variant fuses denom/coef)
    dpfp_kernel<true ><<<dim3(S, NKV), blk>>>(pK, pMK, normv);
    dpfp_kernel<false><<<dim3(S, NH ), blk>>>(pQ, pMQ, nullptr);

    // 3) num = ext_mk @ memory (per head), old memory
    gemm_skinny<<<dim3(S / 128, NH), blk>>>(pMK, 4, (size_t)S * FF,
                                            memv, (size_t)FF * DD,
                                            pNUM, (size_t)S * DD, FF);

    // 4) weighted_mv
    wmv_kernel<<<(NH * S * DD) / 256, blk>>>();

    // 5) delta_memory (split-K=4), delta_norm, then add
    gemm_delta<<<dim3(FF / 128, 4, NH), blk>>>();
    delta_norm_kernel<<<dim3(FF / 64, NKV), blk>>>(normv, out_norm);
    add_delta_kernel<<<MEM_ELEMS / 256, blk>>>(memv, out_mem);

    // 6) associate: den_a, num_a (new memory), output
    dena_kernel<<<dim3(S, NH), blk>>>(out_norm);
    gemm_skinny<<<dim3(S / 128, NH), blk>>>(pMQ, 1, (size_t)S * FF,
                                            out_mem, (size_t)FF * DD,
                                            pNUM, (size_t)S * DD, FF);
    final_kernel<<<OUT_ELEMS / 256, blk>>>(X, out);
}

// round 6
// speedup vs baseline: 1.0003x; 1.0003x over previous
#include <cuda_runtime.h>
#include <math.h>

// ---------------- Problem constants ----------------
#define S      4096
#define HID    2048
#define NH     16
#define NKV    4
#define DD     128
#define FF     768
#define EPSV   1e-8f

#define OUT_ELEMS    (S * HID)            // 8388608
#define MEM_ELEMS    (NH * FF * DD)       // 1572864
#define NORM_ELEMS   (NH * FF)            // 12288

// ---------------- Scratch (device globals; no allocation allowed) ----------------
__device__ __align__(16) float g_K  [S * 512];
__device__ __align__(16) float g_V  [S * 512];
__device__ __align__(16) float g_Q  [S * HID];
__device__ __align__(16) float g_MB [S * HID];
__device__ __align__(16) float g_G  [S * HID];
__device__ __align__(16) float g_MK [(size_t)NKV * S * FF];
__device__ __align__(16) float g_MQ [(size_t)NH * S * FF];
__device__ __align__(16) float g_NUM[(size_t)NH * S * DD];   // reused: num, then num_a
__device__ __align__(16) float g_WMV[(size_t)NH * S * DD];
__device__ __align__(16) float g_DELTA[4][(size_t)NH * FF * DD]; // split-K partials
__device__ float g_DEN [NH * S];
__device__ float g_COEF[NH * S];
__device__ float g_DENA[NH * S];

// ---------------- helpers ----------------
__device__ __forceinline__ float warp_sum(float v) {
#pragma unroll
    for (int o = 16; o > 0; o >>= 1) v += __shfl_down_sync(0xffffffffu, v, o);
    return v;
}

// ======================================================================
// SGEMM: C[M,N] = A[M,K] @ W[N,K]^T + bias, optional sigmoid.
// BM=BN=128, BK=8, 256 threads, 8x8 microtile.
// ======================================================================
template <int ACT>
__global__ __launch_bounds__(256) void sgemm_bias(
    const float* __restrict__ A, const float* __restrict__ W,
    const float* __restrict__ bias, float* __restrict__ C,
    int M, int N, int K)
{
    __shared__ float As[8][128];
    __shared__ float Ws[8][128];
    const int tid = threadIdx.x;
    const int bm = blockIdx.y * 128;
    const int bn = blockIdx.x * 128;
    const int lr = tid >> 1;
    const int lc = (tid & 1) * 4;
    const int ty = (tid >> 4) * 8;
    const int tx = (tid & 15) * 8;

    const float* Ap = A + (size_t)(bm + lr) * K + lc;
    const float* Wp = W + (size_t)(bn + lr) * K + lc;

    float acc[8][8];
#pragma unroll
    for (int i = 0; i < 8; i++)
#pragma unroll
        for (int j = 0; j < 8; j++) acc[i][j] = 0.f;

    for (int k0 = 0; k0 < K; k0 += 8) {
        float4 av = *(const float4*)(Ap + k0);
        float4 wv = *(const float4*)(Wp + k0);
        As[lc + 0][lr] = av.x; As[lc + 1][lr] = av.y;
        As[lc + 2][lr] = av.z; As[lc + 3][lr] = av.w;
        Ws[lc + 0][lr] = wv.x; Ws[lc + 1][lr] = wv.y;
        Ws[lc + 2][lr] = wv.z; Ws[lc + 3][lr] = wv.w;
        __syncthreads();
#pragma unroll
        for (int kk = 0; kk < 8; kk++) {
            float4 a0 = *(const float4*)(&As[kk][ty]);
            float4 a1 = *(const float4*)(&As[kk][ty + 4]);
            float4 b0 = *(const float4*)(&Ws[kk][tx]);
            float4 b1 = *(const float4*)(&Ws[kk][tx + 4]);
            float a[8] = {a0.x, a0.y, a0.z, a0.w, a1.x, a1.y, a1.z, a1.w};
            float b[8] = {b0.x, b0.y, b0.z, b0.w, b1.x, b1.y, b1.z, b1.w};
#pragma unroll
            for (int i = 0; i < 8; i++)
#pragma unroll
                for (int j = 0; j < 8; j++)
                    acc[i][j] = fmaf(a[i], b[j], acc[i][j]);
        }
        __syncthreads();
    }

    float bb[8];
#pragma unroll
    for (int j = 0; j < 8; j++) bb[j] = bias[bn + tx + j];

#pragma unroll
    for (int i = 0; i < 8; i++) {
        float v[8];
#pragma unroll
        for (int j = 0; j < 8; j++) {
            float t = acc[i][j] + bb[j];
            if (ACT) t = 1.f / (1.f + expf(-t));
            v[j] = t;
        }
        float* cp = C + (size_t)(bm + ty + i) * N + bn + tx;
        *(float4*)(cp)     = make_float4(v[0], v[1], v[2], v[3]);
        *(float4*)(cp + 4) = make_float4(v[4], v[5], v[6], v[7]);
    }
}

// ======================================================================
// Skinny GEMM: per head h, C[h][M,128] = A[h/adiv][M,K] @ B[h][K,128].
// A row-major (K contiguous), B row-major (128 contiguous).
// grid = (M/128, NH). Used for num (adiv=4, B=memory) and num_a (adiv=1, B=new_memory).
// ======================================================================
__global__ __launch_bounds__(256) void gemm_skinny(
    const float* __restrict__ Abase, int adiv, size_t a_stride,
    const float* __restrict__ Bbase, size_t b_stride,
    float* __restrict__ Cbase, size_t c_stride, int K)
{
    const int h = blockIdx.y;
    const float* A = Abase + (size_t)(h / adiv) * a_stride;
    const float* B = Bbase + (size_t)h * b_stride;
    float* C = Cbase + (size_t)h * c_stride;

    __shared__ float As[8][128];
    __shared__ float Bs[8][128];
    const int tid = threadIdx.x;
    const int bm = blockIdx.x * 128;
    const int alr = tid >> 1;
    const int alc = (tid & 1) * 4;
    const int bk  = tid >> 5;
    const int bn4 = (tid & 31) * 4;
    const int ty = (tid >> 4) * 8;
    const int tx = (tid & 15) * 8;

    const float* Ap = A + (size_t)(bm + alr) * K + alc;

    float acc[8][8];
#pragma unroll
    for (int i = 0; i < 8; i++)
#pragma unroll
        for (int j = 0; j < 8; j++) acc[i][j] = 0.f;

    for (int k0 = 0; k0 < K; k0 += 8) {
        float4 av = *(const float4*)(Ap + k0);
        float4 bv = *(const float4*)(B + (size_t)(k0 + bk) * 128 + bn4);
        As[alc + 0][alr] = av.x; As[alc + 1][alr] = av.y;
        As[alc + 2][alr] = av.z; As[alc + 3][alr] = av.w;
        *(float4*)(&Bs[bk][bn4]) = bv;
        __syncthreads();
#pragma unroll
        for (int kk = 0; kk < 8; kk++) {
            float4 a0 = *(const float4*)(&As[kk][ty]);
            float4 a1 = *(const float4*)(&As[kk][ty + 4]);
            float4 b0 = *(const float4*)(&Bs[kk][tx]);
            float4 b1 = *(const float4*)(&Bs[kk][tx + 4]);
            float a[8] = {a0.x, a0.y, a0.z, a0.w, a1.x, a1.y, a1.z, a1.w};
            float b[8] = {b0.x, b0.y, b0.z, b0.w, b1.x, b1.y, b1.z, b1.w};
#pragma unroll
            for (int i = 0; i < 8; i++)
#pragma unroll
                for (int j = 0; j < 8; j++)
                    acc[i][j] = fmaf(a[i], b[j], acc[i][j]);
        }
        __syncthreads();
    }

#pragma unroll
    for (int i = 0; i < 8; i++) {
        float* cp = C + (size_t)(bm + ty + i) * 128 + tx;
        *(float4*)(cp)     = make_float4(acc[i][0], acc[i][1], acc[i][2], acc[i][3]);
        *(float4*)(cp + 4) = make_float4(acc[i][4], acc[i][5], acc[i][6], acc[i][7]);
    }
}

// ======================================================================
// Delta GEMM (split-K): DELTA[part][h][f,d] = sum_{s in part} MK[h/4][s,f]*WMV[h][s,d]
// grid = (F/128=6, 4 parts, 16 heads). Both operands are [s][col] panels.
// ======================================================================
__global__ __launch_bounds__(256) void gemm_delta()
{
    const int h    = blockIdx.z;
    const int part = blockIdx.y;
    const int f0   = blockIdx.x * 128;
    const float* A = g_MK + (size_t)(h >> 2) * S * FF;   // [S][F]
    const float* B = g_WMV + (size_t)h * S * DD;         // [S][128]

    __shared__ float As[8][128];
    __shared__ float Bs[8][128];
    const int tid = threadIdx.x;
    const int k  = tid >> 5;
    const int c4 = (tid & 31) * 4;
    const int ty = (tid >> 4) * 8;
    const int tx = (tid & 15) * 8;

    float acc[8][8];
#pragma unroll
    for (int i = 0; i < 8; i++)
#pragma unroll
        for (int j = 0; j < 8; j++) acc[i][j] = 0.f;

    const int kbeg = part * (S / 4);
    const int kend = kbeg + (S / 4);
    for (int k0 = kbeg; k0 < kend; k0 += 8) {
        *(float4*)(&As[k][c4]) = *(const float4*)(A + (size_t)(k0 + k) * FF + f0 + c4);
        *(float4*)(&Bs[k][c4]) = *(const float4*)(B + (size_t)(k0 + k) * 128 + c4);
        __syncthreads();
#pragma unroll
        for (int kk = 0; kk < 8; kk++) {
            float4 a0 = *(const float4*)(&As[kk][ty]);
            float4 a1 = *(const float4*)(&As[kk][ty + 4]);
            float4 b0 = *(const float4*)(&Bs[kk][tx]);
            float4 b1 = *(const float4*)(&Bs[kk][tx + 4]);
            float a[8] = {a0.x, a0.y, a0.z, a0.w, a1.x, a1.y, a1.z, a1.w};
            float b[8] = {b0.x, b0.y, b0.z, b0.w, b1.x, b1.y, b1.z, b1.w};
#pragma unroll
            for (int i = 0; i < 8; i++)
#pragma unroll
                for (int j = 0; j < 8; j++)
                    acc[i][j] = fmaf(a[i], b[j], acc[i][j]);
        }
        __syncthreads();
    }

    float* Cp = g_DELTA[part] + (size_t)h * FF * DD;
#pragma unroll
    for (int i = 0; i < 8; i++) {
        float* cp = Cp + (size_t)(f0 + ty + i) * 128 + tx;
        *(float4*)(cp)     = make_float4(acc[i][0], acc[i][1], acc[i][2], acc[i][3]);
        *(float4*)(cp + 4) = make_float4(acc[i][4], acc[i][5], acc[i][6], acc[i][7]);
    }
}

// ======================================================================
// dpfp + L2-normalize. grid=(S, nheads). 256 threads.
// mk[j*256+i] = y[i]*y[(i-j-1) mod 256], j=0..2, y = [relu(x), relu(-x)].
// WITHDEN: also fuse denom[h,s] = dot(mk_norm, norm[h]) + EPS and coef.
// ======================================================================
template <bool WITHDEN>
__global__ __launch_bounds__(256) void dpfp_kernel(
    const float* __restrict__ X, float* __restrict__ mkout,
    const float* __restrict__ normv)
{
    const int s  = blockIdx.x;
    const int hh = blockIdx.y;
    const int nh = gridDim.y;
    const int t  = threadIdx.x;
    __shared__ float y[256];
    __shared__ float red[5][8];

    const float* x = X + ((size_t)s * nh + hh) * 128;
    float xv = (t < 128) ? x[t] : -x[t - 128];
    y[t] = fmaxf(xv, 0.f);
    __syncthreads();

    float yi = y[t];
    float m0 = yi * y[(t - 1) & 255];
    float m1 = yi * y[(t - 2) & 255];
    float m2 = yi * y[(t - 3) & 255];
    float ss = m0 * m0 + m1 * m1 + m2 * m2;

    float dd[4];
    if (WITHDEN) {
#pragma unroll
        for (int g = 0; g < 4; g++) {
            const float* nr = normv + (size_t)(4 * hh + g) * FF;
            dd[g] = m0 * nr[t] + m1 * nr[256 + t] + m2 * nr[512 + t];
        }
    }

    const int lane = t & 31, w = t >> 5;
    float r0 = warp_sum(ss);
    if (lane == 0) red[0][w] = r0;
    if (WITHDEN) {
#pragma unroll
        for (int g = 0; g < 4; g++) {
            float rg = warp_sum(dd[g]);
            if (lane == 0) red[1 + g][w] = rg;
        }
    }
    __syncthreads();

    float ssT = 0.f;
#pragma unroll
    for (int w2 = 0; w2 < 8; w2++) ssT += red[0][w2];
    float nrm = sqrtf(ssT);
    float inv = 1.f / fmaxf(nrm, 1e-12f);

    float* o = mkout + ((size_t)hh * S + s) * FF;
    o[t]       = m0 * inv;
    o[256 + t] = m1 * inv;
    o[512 + t] = m2 * inv;

    if (WITHDEN && t < 4) {
        float dT = 0.f;
#pragma unroll
        for (int w2 = 0; w2 < 8; w2++) dT += red[1 + t][w2];
        float den  = dT * inv + EPSV;
        float mksq = ssT * inv * inv;
        float coef = 1.f - den / mksq;
        coef = fminf(fmaxf(coef, 0.f), 1.f);
        int h = 4 * hh + t;
        g_DEN[h * S + s]  = den;
        g_COEF[h * S + s] = coef;
    }
}

// ======================================================================
// weighted_mv = (v - num/denom) * mb. NH*S*D elements.
// ======================================================================
__global__ void wmv_kernel()
{
    size_t idx = (size_t)blockIdx.x * 256 + threadIdx.x;
    int h = (int)(idx >> 19);             // S*D = 2^19
    size_t r = idx & ((1u << 19) - 1);
    int s  = (int)(r >> 7);
    int d0 = (int)(r & 127);
    float den  = g_DEN[h * S + s];
    float prev = g_NUM[idx] / den;
    float v  = g_V[(size_t)s * 512 + (size_t)(h >> 2) * 128 + d0];
    float mb = g_MB[(size_t)s * HID + (size_t)h * 128 + d0];
    g_WMV[idx] = (v - prev) * mb;
}

// ======================================================================
// new_norm[h][f] = norm[h][f] + sum_s coef[h][s]*MK[h/4][s][f]
// grid = (F/64=12, NKV). 256 threads: 64 f-lanes x 4 s-lanes.
// ======================================================================
__global__ __launch_bounds__(256) void delta_norm_kernel(
    const float* __restrict__ normv, float* __restrict__ out_norm)
{
    const int kv = blockIdx.y;
    const int f0 = blockIdx.x * 64;
    const int t  = threadIdx.x;
    const int fl = t & 63, sl = t >> 6;

    float acc[4] = {0.f, 0.f, 0.f, 0.f};
    const float* mkbase = g_MK + (size_t)kv * S * FF + f0 + fl;
    for (int s = sl; s < S; s += 4) {
        float v = mkbase[(size_t)s * FF];
#pragma unroll
        for (int g = 0; g < 4; g++)
            acc[g] = fmaf(g_COEF[(4 * kv + g) * S + s], v, acc[g]);
    }
    __shared__ float sm[4][4][64];
#pragma unroll
    for (int g = 0; g < 4; g++) sm[sl][g][fl] = acc[g];
    __syncthreads();
    if (t < 64) {
#pragma unroll
        for (int g = 0; g < 4; g++) {
            float sum = sm[0][g][t] + sm[1][g][t] + sm[2][g][t] + sm[3][g][t];
            int h = 4 * kv + g;
            out_norm[(size_t)h * FF + f0 + t] = normv[(size_t)h * FF + f0 + t] + sum;
        }
    }
}

// new_memory = memory + sum of split-K partials
__global__ void add_delta_kernel(const float* __restrict__ memory,
                                 float* __restrict__ out_mem)
{
    size_t idx = (size_t)blockIdx.x * 256 + threadIdx.x;
    out_mem[idx] = memory[idx] + g_DELTA[0][idx] + g_DELTA[1][idx]
                 + g_DELTA[2][idx] + g_DELTA[3][idx];
}

// den_a[h,s] = dot(mq[h,s], new_norm[h]) + EPS. grid=(S,NH).
__global__ __launch_bounds__(256) void dena_kernel(const float* __restrict__ newnorm)
{
    const int s = blockIdx.x, h = blockIdx.y;
    const int t = threadIdx.x;
    const float* mq = g_MQ + ((size_t)h * S + s) * FF;
    const float* nr = newnorm + (size_t)h * FF;
    float dd = mq[t] * nr[t] + mq[256 + t] * nr[256 + t] + mq[512 + t] * nr[512 + t];
    __shared__ float red[8];
    float r = warp_sum(dd);
    if ((t & 31) == 0) red[t >> 5] = r;
    __syncthreads();
    if (t == 0) {
        float s8 = 0.f;
#pragma unroll
        for (int w = 0; w < 8; w++) s8 += red[w];
        g_DENA[h * S + s] = s8 + EPSV;
    }
}

// out = hidden + gate * (num_a / den_a) with [B,H,S,D]->[S,HID] transpose
__global__ void final_kernel(const float* __restrict__ X, float* __restrict__ out)
{
    size_t idx = (size_t)blockIdx.x * 256 + threadIdx.x;
    int s  = (int)(idx >> 11);
    int c  = (int)(idx & 2047);
    int h  = c >> 7;
    int d0 = c & 127;
    float numa = g_NUM[((size_t)h * S + s) * DD + d0];
    float mh = numa / g_DENA[h * S + s];
    out[idx] = X[idx] + g_G[idx] * mh;
}

// ======================================================================
// Launch
// ======================================================================
extern "C" void kernel_launch(void* const* d_in, const int* in_sizes, int n_in,
                              void* d_out, int out_size)
{
    const float* X    = (const float*)d_in[0];
    const float* Wq   = (const float*)d_in[1];
    const float* bq   = (const float*)d_in[2];
    const float* Wk   = (const float*)d_in[3];
    const float* bk   = (const float*)d_in[4];
    const float* Wv   = (const float*)d_in[5];
    const float* bv   = (const float*)d_in[6];
    const float* Wg   = (const float*)d_in[7];
    const float* bg   = (const float*)d_in[8];
    const float* Wmb  = (const float*)d_in[9];
    const float* bmb  = (const float*)d_in[10];
    const float* memv = (const float*)d_in[11];
    const float* normv= (const float*)d_in[12];

    float* out      = (float*)d_out;
    float* out_mem  = out + OUT_ELEMS;
    float* out_norm = out_mem + MEM_ELEMS;

    float *pK, *pV, *pQ, *pMB, *pG, *pMK, *pMQ, *pNUM;
    cudaGetSymbolAddress((void**)&pK,  g_K);
    cudaGetSymbolAddress((void**)&pV,  g_V);
    cudaGetSymbolAddress((void**)&pQ,  g_Q);
    cudaGetSymbolAddress((void**)&pMB, g_MB);
    cudaGetSymbolAddress((void**)&pG,  g_G);
    cudaGetSymbolAddress((void**)&pMK, g_MK);
    cudaGetSymbolAddress((void**)&pMQ, g_MQ);
    cudaGetSymbolAddress((void**)&pNUM, g_NUM);

    dim3 blk(256);

    // 1) Projections
    sgemm_bias<0><<<dim3(HID / 128, S / 128), blk>>>(X, Wq,  bq,  pQ,  S, HID, HID);
    sgemm_bias<0><<<dim3(512 / 128, S / 128), blk>>>(X, Wk,  bk,  pK,  S, 512, HID);
    sgemm_bias<0><<<dim3(512 / 128, S / 128), blk>>>(X, Wv,  bv,  pV,  S, 512, HID);
    sgemm_bias<1><<<dim3(HID / 128, S / 128), blk>>>(X, Wmb, bmb, pMB, S, HID, HID);
    sgemm_bias<1><<<dim3(HID / 128, S / 128), blk>>>(X, Wg,  bg,  pG,  S, HID, HID);

    // 2) dpfp + normalize (K variant fuses denom/coef)
    dpfp_kernel<true ><<<dim3(S, NKV), blk>>>(pK, pMK, normv);
    dpfp_kernel<false><<<dim3(S, NH ), blk>>>(pQ, pMQ, nullptr);

    // 3) num = ext_mk @ memory (per head), old memory
    gemm_skinny<<<dim3(S / 128, NH), blk>>>(pMK, 4, (size_t)S * FF,
                                            memv, (size_t)FF * DD,
                                            pNUM, (size_t)S * DD, FF);

    // 4) weighted_mv
    wmv_kernel<<<(NH * S * DD) / 256, blk>>>();

    // 5) delta_memory (split-K=4), delta_norm, then add
    gemm_delta<<<dim3(FF / 128, 4, NH), blk>>>();
    delta_norm_kernel<<<dim3(FF / 64, NKV), blk>>>(normv, out_norm);
    add_delta_kernel<<<MEM_ELEMS / 256, blk>>>(memv, out_mem);

    // 6) associate: den_a, num_a (new memory), output
    dena_kernel<<<dim3(S, NH), blk>>>(out_norm);
    gemm_skinny<<<dim3(S / 128, NH), blk>>>(pMQ, 1, (size_t)S * FF,
                                            out_mem, (size_t)FF * DD,
                                            pNUM, (size_t)S * DD, FF);
    final_kernel<<<OUT_ELEMS / 256, blk>>>(X, out);
}

// round 8
// speedup vs baseline: 1.7624x; 1.7620x over previous
#include <cuda_runtime.h>
#include <cuda_bf16.h>
#include <math.h>
#include <stdint.h>

// ---------------- Problem constants ----------------
#define S      4096
#define HID    2048
#define NH     16
#define NKV    4
#define DD     128
#define FF     768
#define EPSV   1e-8f

#define OUT_ELEMS    (S * HID)
#define MEM_ELEMS    (NH * FF * DD)

// ---------------- Scratch (device globals; no allocation allowed) ----------------
__device__ __align__(16) float g_K  [S * 512];
__device__ __align__(16) float g_V  [S * 512];
__device__ __align__(16) float g_Q  [S * HID];
__device__ __align__(16) float g_MB [S * HID];
__device__ __align__(16) float g_G  [S * HID];
__device__ __align__(16) float g_MK [(size_t)NKV * S * FF];
__device__ __align__(16) float g_MQ [(size_t)NH * S * FF];
__device__ __align__(16) float g_NUM[(size_t)NH * S * DD];
__device__ __align__(16) float g_WMV[(size_t)NH * S * DD];
__device__ __align__(16) float g_DELTA[4][(size_t)NH * FF * DD];
__device__ float g_DEN [NH * S];
__device__ float g_COEF[NH * S];
__device__ float g_DENA[NH * S];

// bf16 split operands for tensor-core projections
__device__ __align__(16) __nv_bfloat16 g_XH [S * HID];
__device__ __align__(16) __nv_bfloat16 g_XL [S * HID];
__device__ __align__(16) __nv_bfloat16 g_WqH[HID * HID], g_WqL[HID * HID];
__device__ __align__(16) __nv_bfloat16 g_WmH[HID * HID], g_WmL[HID * HID];
__device__ __align__(16) __nv_bfloat16 g_WgH[HID * HID], g_WgL[HID * HID];
__device__ __align__(16) __nv_bfloat16 g_WkH[512 * HID], g_WkL[512 * HID];
__device__ __align__(16) __nv_bfloat16 g_WvH[512 * HID], g_WvL[512 * HID];

// ---------------- helpers ----------------
__device__ __forceinline__ float warp_sum(float v) {
#pragma unroll
    for (int o = 16; o > 0; o >>= 1) v += __shfl_down_sync(0xffffffffu, v, o);
    return v;
}
__device__ __forceinline__ uint32_t smem_u32(const void* p) {
    uint32_t a;
    asm("{ .reg .u64 t; cvta.to.shared.u64 t, %1; cvt.u32.u64 %0, t; }"
        : "=r"(a) : "l"(p));
    return a;
}
__device__ __forceinline__ void cp_async16(uint32_t sa, const void* g) {
    asm volatile("cp.async.cg.shared.global [%0], [%1], 16;" :: "r"(sa), "l"(g) : "memory");
}
__device__ __forceinline__ void cp_commit() {
    asm volatile("cp.async.commit_group;" ::: "memory");
}
template<int N> __device__ __forceinline__ void cp_wait() {
    asm volatile("cp.async.wait_group %0;" :: "n"(N) : "memory");
}
__device__ __forceinline__ void ldm_x4(uint32_t* r, uint32_t addr) {
    asm volatile("ldmatrix.sync.aligned.m8n8.x4.shared.b16 {%0,%1,%2,%3}, [%4];"
                 : "=r"(r[0]), "=r"(r[1]), "=r"(r[2]), "=r"(r[3]) : "r"(addr));
}
__device__ __forceinline__ void ldm_x2(uint32_t* r, uint32_t addr) {
    asm volatile("ldmatrix.sync.aligned.m8n8.x2.shared.b16 {%0,%1}, [%2];"
                 : "=r"(r[0]), "=r"(r[1]) : "r"(addr));
}
__device__ __forceinline__ void mma_bf16(float* c, const uint32_t* a, const uint32_t* b) {
    asm volatile(
        "mma.sync.aligned.m16n8k16.row.col.f32.bf16.bf16.f32 "
        "{%0,%1,%2,%3}, {%4,%5,%6,%7}, {%8,%9}, {%0,%1,%2,%3};"
        : "+f"(c[0]), "+f"(c[1]), "+f"(c[2]), "+f"(c[3])
        : "r"(a[0]), "r"(a[1]), "r"(a[2]), "r"(a[3]), "r"(b[0]), "r"(b[1]));
}

// ======================================================================
// fp32 -> bf16 hi/lo split conversion (vectorized x4)
// ======================================================================
__global__ void cvt_split(const float* __restrict__ x,
                          __nv_bfloat16* __restrict__ hi,
                          __nv_bfloat16* __restrict__ lo, int n4)
{
    int i = blockIdx.x * 256 + threadIdx.x;
    if (i >= n4) return;
    float4 v = ((const float4*)x)[i];
    __nv_bfloat16 h0 = __float2bfloat16(v.x), h1 = __float2bfloat16(v.y);
    __nv_bfloat16 h2 = __float2bfloat16(v.z), h3 = __float2bfloat16(v.w);
    __nv_bfloat16 l0 = __float2bfloat16(v.x - __bfloat162float(h0));
    __nv_bfloat16 l1 = __float2bfloat16(v.y - __bfloat162float(h1));
    __nv_bfloat16 l2 = __float2bfloat16(v.z - __bfloat162float(h2));
    __nv_bfloat16 l3 = __float2bfloat16(v.w - __bfloat162float(h3));
    __nv_bfloat162* hp = (__nv_bfloat162*)hi;
    __nv_bfloat162* lp = (__nv_bfloat162*)lo;
    hp[2 * i]     = __nv_bfloat162(h0, h1);
    hp[2 * i + 1] = __nv_bfloat162(h2, h3);
    lp[2 * i]     = __nv_bfloat162(l0, l1);
    lp[2 * i + 1] = __nv_bfloat162(l2, l3);
}

// ======================================================================
// Tensor-core bf16-split GEMM via mma.sync (baseline PTX, no tcgen05):
// C[M,N] = A[M,K] @ W[N,K]^T + bias (opt sigmoid); fp32 accumulate.
// 128x128 CTA tile, 8 warps (2x4), warp tile 64x32, BK=32,
// 2-stage cp.async pipeline. 3 products: Ah*Bh + Ah*Bl + Al*Bh.
// SMEM rows padded to 40 bf16 (80B) -> conflict-free ldmatrix.
// ======================================================================
#define MMA_TILE_B   10240              // 128 rows * 80 bytes
#define MMA_STAGE_B  (4 * MMA_TILE_B)   // Ahi, Alo, Bhi, Blo
#define MMA_SMEM     (2 * MMA_STAGE_B)  // 81920 bytes

template <int ACT>
__global__ __launch_bounds__(256, 1) void gemm_mma(
    const __nv_bfloat16* __restrict__ Ahi, const __nv_bfloat16* __restrict__ Alo,
    const __nv_bfloat16* __restrict__ Bhi, const __nv_bfloat16* __restrict__ Blo,
    const float* __restrict__ bias, float* __restrict__ C, int N, int K)
{
    extern __shared__ char sm[];
    const int tid  = threadIdx.x;
    const int lane = tid & 31;
    const int warp = tid >> 5;
    const int wm = warp >> 2;           // 0..1
    const int wn = warp & 3;            // 0..3
    const int bm = blockIdx.y * 128;
    const int bn = blockIdx.x * 128;
    const uint32_t sbase = smem_u32(sm);

    const __nv_bfloat16* srcs[4] = {Ahi, Alo, Bhi, Blo};
    const int rb4[4] = {bm, bm, bn, bn};

    auto load_chunk = [&](int c, int st) {
        const int k0 = c << 5;
        const uint32_t stb = sbase + (uint32_t)st * MMA_STAGE_B;
#pragma unroll
        for (int tile = 0; tile < 4; ++tile) {
            const __nv_bfloat16* src = srcs[tile] + (size_t)rb4[tile] * K + k0;
#pragma unroll
            for (int rep = 0; rep < 2; ++rep) {
                int i = tid + rep * 256;            // 0..511
                int r = i >> 2, cc = i & 3;          // row, 16B-chunk
                cp_async16(stb + (uint32_t)tile * MMA_TILE_B + r * 80 + cc * 16,
                           src + (size_t)r * K + cc * 8);
            }
        }
        cp_commit();
    };

    float acc[4][4][4];
#pragma unroll
    for (int mt = 0; mt < 4; ++mt)
#pragma unroll
        for (int nt = 0; nt < 4; ++nt)
#pragma unroll
            for (int r = 0; r < 4; ++r) acc[mt][nt][r] = 0.f;

    const int NC = K >> 5;
    load_chunk(0, 0);

    for (int c = 0; c < NC; ++c) {
        const int st = c & 1;
        if (c + 1 < NC) { load_chunk(c + 1, st ^ 1); cp_wait<1>(); }
        else            { cp_wait<0>(); }
        __syncthreads();

        const uint32_t stb = sbase + (uint32_t)st * MMA_STAGE_B;
#pragma unroll
        for (int k16 = 0; k16 < 2; ++k16) {
            uint32_t ah[4][4], al[4][4];
#pragma unroll
            for (int mt = 0; mt < 4; ++mt) {
                uint32_t rowa = (uint32_t)(wm * 64 + mt * 16 + (lane & 15));
                uint32_t coff = (uint32_t)((k16 * 16 + ((lane >> 4) << 3)) * 2);
                ldm_x4(ah[mt], stb + 0 * MMA_TILE_B + rowa * 80 + coff);
                ldm_x4(al[mt], stb + 1 * MMA_TILE_B + rowa * 80 + coff);
            }
#pragma unroll
            for (int nt = 0; nt < 4; ++nt) {
                uint32_t rowb = (uint32_t)(wn * 32 + nt * 8 + (lane & 7));
                uint32_t coff = (uint32_t)((k16 * 16 + (((lane >> 3) & 1) << 3)) * 2);
                uint32_t bh[2], bl[2];
                ldm_x2(bh, stb + 2 * MMA_TILE_B + rowb * 80 + coff);
                ldm_x2(bl, stb + 3 * MMA_TILE_B + rowb * 80 + coff);
#pragma unroll
                for (int mt = 0; mt < 4; ++mt) {
                    mma_bf16(acc[mt][nt], ah[mt], bh);
                    mma_bf16(acc[mt][nt], ah[mt], bl);
                    mma_bf16(acc[mt][nt], al[mt], bh);
                }
            }
        }
        __syncthreads();
    }

    // Epilogue: bias (+sigmoid), float2 stores
    const int r0 = bm + wm * 64;
    const int c0 = bn + wn * 32;
    const int rl = lane >> 2;
    const int cl = (lane & 3) * 2;
#pragma unroll
    for (int mt = 0; mt < 4; ++mt) {
#pragma unroll
        for (int nt = 0; nt < 4; ++nt) {
            int col = c0 + nt * 8 + cl;
            float b0 = bias[col], b1 = bias[col + 1];
#pragma unroll
            for (int half = 0; half < 2; ++half) {
                int row = r0 + mt * 16 + rl + half * 8;
                float v0 = acc[mt][nt][2 * half + 0] + b0;
                float v1 = acc[mt][nt][2 * half + 1] + b1;
                if (ACT) {
                    v0 = 1.f / (1.f + expf(-v0));
                    v1 = 1.f / (1.f + expf(-v1));
                }
                *(float2*)(C + (size_t)row * N + col) = make_float2(v0, v1);
            }
        }
    }
}

// ======================================================================
// Skinny GEMM (fp32): per head h, C[h][M,128] = A[h/adiv][M,K] @ B[h][K,128]
// ======================================================================
__global__ __launch_bounds__(256) void gemm_skinny(
    const float* __restrict__ Abase, int adiv, size_t a_stride,
    const float* __restrict__ Bbase, size_t b_stride,
    float* __restrict__ Cbase, size_t c_stride, int K)
{
    const int h = blockIdx.y;
    const float* A = Abase + (size_t)(h / adiv) * a_stride;
    const float* B = Bbase + (size_t)h * b_stride;
    float* C = Cbase + (size_t)h * c_stride;

    __shared__ float As[8][128];
    __shared__ float Bs[8][128];
    const int tid = threadIdx.x;
    const int bm = blockIdx.x * 128;
    const int alr = tid >> 1;
    const int alc = (tid & 1) * 4;
    const int bk  = tid >> 5;
    const int bn4 = (tid & 31) * 4;
    const int ty = (tid >> 4) * 8;
    const int tx = (tid & 15) * 8;

    const float* Ap = A + (size_t)(bm + alr) * K + alc;

    float acc[8][8];
#pragma unroll
    for (int i = 0; i < 8; i++)
#pragma unroll
        for (int j = 0; j < 8; j++) acc[i][j] = 0.f;

    for (int k0 = 0; k0 < K; k0 += 8) {
        float4 av = *(const float4*)(Ap + k0);
        float4 bv = *(const float4*)(B + (size_t)(k0 + bk) * 128 + bn4);
        As[alc + 0][alr] = av.x; As[alc + 1][alr] = av.y;
        As[alc + 2][alr] = av.z; As[alc + 3][alr] = av.w;
        *(float4*)(&Bs[bk][bn4]) = bv;
        __syncthreads();
#pragma unroll
        for (int kk = 0; kk < 8; kk++) {
            float4 a0 = *(const float4*)(&As[kk][ty]);
            float4 a1 = *(const float4*)(&As[kk][ty + 4]);
            float4 b0 = *(const float4*)(&Bs[kk][tx]);
            float4 b1 = *(const float4*)(&Bs[kk][tx + 4]);
            float a[8] = {a0.x, a0.y, a0.z, a0.w, a1.x, a1.y, a1.z, a1.w};
            float b[8] = {b0.x, b0.y, b0.z, b0.w, b1.x, b1.y, b1.z, b1.w};
#pragma unroll
            for (int i = 0; i < 8; i++)
#pragma unroll
                for (int j = 0; j < 8; j++)
                    acc[i][j] = fmaf(a[i], b[j], acc[i][j]);
        }
        __syncthreads();
    }

#pragma unroll
    for (int i = 0; i < 8; i++) {
        float* cp = C + (size_t)(bm + ty + i) * 128 + tx;
        *(float4*)(cp)     = make_float4(acc[i][0], acc[i][1], acc[i][2], acc[i][3]);
        *(float4*)(cp + 4) = make_float4(acc[i][4], acc[i][5], acc[i][6], acc[i][7]);
    }
}

// ======================================================================
// Delta GEMM (split-K): DELTA[part][h][f,d] = sum_{s in part} MK[h/4][s,f]*WMV[h][s,d]
// ======================================================================
__global__ __launch_bounds__(256) void gemm_delta()
{
    const int h    = blockIdx.z;
    const int part = blockIdx.y;
    const int f0   = blockIdx.x * 128;
    const float* A = g_MK + (size_t)(h >> 2) * S * FF;
    const float* B = g_WMV + (size_t)h * S * DD;

    __shared__ float As[8][128];
    __shared__ float Bs[8][128];
    const int tid = threadIdx.x;
    const int k  = tid >> 5;
    const int c4 = (tid & 31) * 4;
    const int ty = (tid >> 4) * 8;
    const int tx = (tid & 15) * 8;

    float acc[8][8];
#pragma unroll
    for (int i = 0; i < 8; i++)
#pragma unroll
        for (int j = 0; j < 8; j++) acc[i][j] = 0.f;

    const int kbeg = part * (S / 4);
    const int kend = kbeg + (S / 4);
    for (int k0 = kbeg; k0 < kend; k0 += 8) {
        *(float4*)(&As[k][c4]) = *(const float4*)(A + (size_t)(k0 + k) * FF + f0 + c4);
        *(float4*)(&Bs[k][c4]) = *(const float4*)(B + (size_t)(k0 + k) * 128 + c4);
        __syncthreads();
#pragma unroll
        for (int kk = 0; kk < 8; kk++) {
            float4 a0 = *(const float4*)(&As[kk][ty]);
            float4 a1 = *(const float4*)(&As[kk][ty + 4]);
            float4 b0 = *(const float4*)(&Bs[kk][tx]);
            float4 b1 = *(const float4*)(&Bs[kk][tx + 4]);
            float a[8] = {a0.x, a0.y, a0.z, a0.w, a1.x, a1.y, a1.z, a1.w};
            float b[8] = {b0.x, b0.y, b0.z, b0.w, b1.x, b1.y, b1.z, b1.w};
#pragma unroll
            for (int i = 0; i < 8; i++)
#pragma unroll
                for (int j = 0; j < 8; j++)
                    acc[i][j] = fmaf(a[i], b[j], acc[i][j]);
        }
        __syncthreads();
    }

    float* Cp = g_DELTA[part] + (size_t)h * FF * DD;
#pragma unroll
    for (int i = 0; i < 8; i++) {
        float* cp = Cp + (size_t)(f0 + ty + i) * 128 + tx;
        *(float4*)(cp)     = make_float4(acc[i][0], acc[i][1], acc[i][2], acc[i][3]);
        *(float4*)(cp + 4) = make_float4(acc[i][4], acc[i][5], acc[i][6], acc[i][7]);
    }
}

// ======================================================================
// dpfp + L2-normalize (K variant fuses denom/coef)
// ======================================================================
template <bool WITHDEN>
__global__ __launch_bounds__(256) void dpfp_kernel(
    const float* __restrict__ X, float* __restrict__ mkout,
    const float* __restrict__ normv)
{
    const int s  = blockIdx.x;
    const int hh = blockIdx.y;
    const int nh = gridDim.y;
    const int t  = threadIdx.x;
    __shared__ float y[256];
    __shared__ float red[5][8];

    const float* x = X + ((size_t)s * nh + hh) * 128;
    float xv = (t < 128) ? x[t] : -x[t - 128];
    y[t] = fmaxf(xv, 0.f);
    __syncthreads();

    float yi = y[t];
    float m0 = yi * y[(t - 1) & 255];
    float m1 = yi * y[(t - 2) & 255];
    float m2 = yi * y[(t - 3) & 255];
    float ss = m0 * m0 + m1 * m1 + m2 * m2;

    float dd[4];
    if (WITHDEN) {
#pragma unroll
        for (int g = 0; g < 4; g++) {
            const float* nr = normv + (size_t)(4 * hh + g) * FF;
            dd[g] = m0 * nr[t] + m1 * nr[256 + t] + m2 * nr[512 + t];
        }
    }

    const int lane = t & 31, w = t >> 5;
    float r0 = warp_sum(ss);
    if (lane == 0) red[0][w] = r0;
    if (WITHDEN) {
#pragma unroll
        for (int g = 0; g < 4; g++) {
            float rg = warp_sum(dd[g]);
            if (lane == 0) red[1 + g][w] = rg;
        }
    }
    __syncthreads();

    float ssT = 0.f;
#pragma unroll
    for (int w2 = 0; w2 < 8; w2++) ssT += red[0][w2];
    float nrm = sqrtf(ssT);
    float inv = 1.f / fmaxf(nrm, 1e-12f);

    float* o = mkout + ((size_t)hh * S + s) * FF;
    o[t]       = m0 * inv;
    o[256 + t] = m1 * inv;
    o[512 + t] = m2 * inv;

    if (WITHDEN && t < 4) {
        float dT = 0.f;
#pragma unroll
        for (int w2 = 0; w2 < 8; w2++) dT += red[1 + t][w2];
        float den  = dT * inv + EPSV;
        float mksq = ssT * inv * inv;
        float coef = 1.f - den / mksq;
        coef = fminf(fmaxf(coef, 0.f), 1.f);
        int h = 4 * hh + t;
        g_DEN[h * S + s]  = den;
        g_COEF[h * S + s] = coef;
    }
}

// weighted_mv = (v - num/denom) * mb
__global__ void wmv_kernel()
{
    size_t idx = (size_t)blockIdx.x * 256 + threadIdx.x;
    int h = (int)(idx >> 19);
    size_t r = idx & ((1u << 19) - 1);
    int s  = (int)(r >> 7);
    int d0 = (int)(r & 127);
    float den  = g_DEN[h * S + s];
    float prev = g_NUM[idx] / den;
    float v  = g_V[(size_t)s * 512 + (size_t)(h >> 2) * 128 + d0];
    float mb = g_MB[(size_t)s * HID + (size_t)h * 128 + d0];
    g_WMV[idx] = (v - prev) * mb;
}

// new_norm[h][f] = norm[h][f] + sum_s coef[h][s]*MK[h/4][s][f]
__global__ __launch_bounds__(256) void delta_norm_kernel(
    const float* __restrict__ normv, float* __restrict__ out_norm)
{
    const int kv = blockIdx.y;
    const int f0 = blockIdx.x * 64;
    const int t  = threadIdx.x;
    const int fl = t & 63, sl = t >> 6;

    float acc[4] = {0.f, 0.f, 0.f, 0.f};
    const float* mkbase = g_MK + (size_t)kv * S * FF + f0 + fl;
    for (int s = sl; s < S; s += 4) {
        float v = mkbase[(size_t)s * FF];
#pragma unroll
        for (int g = 0; g < 4; g++)
            acc[g] = fmaf(g_COEF[(4 * kv + g) * S + s], v, acc[g]);
    }
    __shared__ float smr[4][4][64];
#pragma unroll
    for (int g = 0; g < 4; g++) smr[sl][g][fl] = acc[g];
    __syncthreads();
    if (t < 64) {
#pragma unroll
        for (int g = 0; g < 4; g++) {
            float sum = smr[0][g][t] + smr[1][g][t] + smr[2][g][t] + smr[3][g][t];
            int h = 4 * kv + g;
            out_norm[(size_t)h * FF + f0 + t] = normv[(size_t)h * FF + f0 + t] + sum;
        }
    }
}

__global__ void add_delta_kernel(const float* __restrict__ memory,
                                 float* __restrict__ out_mem)
{
    size_t idx = (size_t)blockIdx.x * 256 + threadIdx.x;
    out_mem[idx] = memory[idx] + g_DELTA[0][idx] + g_DELTA[1][idx]
                 + g_DELTA[2][idx] + g_DELTA[3][idx];
}

__global__ __launch_bounds__(256) void dena_kernel(const float* __restrict__ newnorm)
{
    const int s = blockIdx.x, h = blockIdx.y;
    const int t = threadIdx.x;
    const float* mq = g_MQ + ((size_t)h * S + s) * FF;
    const float* nr = newnorm + (size_t)h * FF;
    float dd = mq[t] * nr[t] + mq[256 + t] * nr[256 + t] + mq[512 + t] * nr[512 + t];
    __shared__ float red[8];
    float r = warp_sum(dd);
    if ((t & 31) == 0) red[t >> 5] = r;
    __syncthreads();
    if (t == 0) {
        float s8 = 0.f;
#pragma unroll
        for (int w = 0; w < 8; w++) s8 += red[w];
        g_DENA[h * S + s] = s8 + EPSV;
    }
}

__global__ void final_kernel(const float* __restrict__ X, float* __restrict__ out)
{
    size_t idx = (size_t)blockIdx.x * 256 + threadIdx.x;
    int s  = (int)(idx >> 11);
    int c  = (int)(idx & 2047);
    int h  = c >> 7;
    int d0 = c & 127;
    float numa = g_NUM[((size_t)h * S + s) * DD + d0];
    float mh = numa / g_DENA[h * S + s];
    out[idx] = X[idx] + g_G[idx] * mh;
}

// ======================================================================
// Launch
// ======================================================================
extern "C" void kernel_launch(void* const* d_in, const int* in_sizes, int n_in,
                              void* d_out, int out_size)
{
    const float* X    = (const float*)d_in[0];
    const float* Wq   = (const float*)d_in[1];
    const float* bq   = (const float*)d_in[2];
    const float* Wk   = (const float*)d_in[3];
    const float* bk   = (const float*)d_in[4];
    const float* Wv   = (const float*)d_in[5];
    const float* bv   = (const float*)d_in[6];
    const float* Wg   = (const float*)d_in[7];
    const float* bg   = (const float*)d_in[8];
    const float* Wmb  = (const float*)d_in[9];
    const float* bmb  = (const float*)d_in[10];
    const float* memv = (const float*)d_in[11];
    const float* normv= (const float*)d_in[12];

    float* out      = (float*)d_out;
    float* out_mem  = out + OUT_ELEMS;
    float* out_norm = out_mem + MEM_ELEMS;

    float *pK, *pV, *pQ, *pMB, *pG, *pMK, *pMQ, *pNUM;
    cudaGetSymbolAddress((void**)&pK,  g_K);
    cudaGetSymbolAddress((void**)&pV,  g_V);
    cudaGetSymbolAddress((void**)&pQ,  g_Q);
    cudaGetSymbolAddress((void**)&pMB, g_MB);
    cudaGetSymbolAddress((void**)&pG,  g_G);
    cudaGetSymbolAddress((void**)&pMK, g_MK);
    cudaGetSymbolAddress((void**)&pMQ, g_MQ);
    cudaGetSymbolAddress((void**)&pNUM, g_NUM);

    __nv_bfloat16 *xh, *xl, *wqh, *wql, *wmh, *wml, *wgh, *wgl, *wkh, *wkl, *wvh, *wvl;
    cudaGetSymbolAddress((void**)&xh,  g_XH);  cudaGetSymbolAddress((void**)&xl,  g_XL);
    cudaGetSymbolAddress((void**)&wqh, g_WqH); cudaGetSymbolAddress((void**)&wql, g_WqL);
    cudaGetSymbolAddress((void**)&wmh, g_WmH); cudaGetSymbolAddress((void**)&wml, g_WmL);
    cudaGetSymbolAddress((void**)&wgh, g_WgH); cudaGetSymbolAddress((void**)&wgl, g_WgL);
    cudaGetSymbolAddress((void**)&wkh, g_WkH); cudaGetSymbolAddress((void**)&wkl, g_WkL);
    cudaGetSymbolAddress((void**)&wvh, g_WvH); cudaGetSymbolAddress((void**)&wvl, g_WvL);

    cudaFuncSetAttribute(gemm_mma<0>, cudaFuncAttributeMaxDynamicSharedMemorySize, MMA_SMEM);
    cudaFuncSetAttribute(gemm_mma<1>, cudaFuncAttributeMaxDynamicSharedMemorySize, MMA_SMEM);

    dim3 blk(256);

    // 0) fp32 -> bf16 hi/lo splits
    cvt_split<<<(S * HID / 4 + 255) / 256, blk>>>(X,   xh,  xl,  S * HID / 4);
    cvt_split<<<(HID * HID / 4 + 255) / 256, blk>>>(Wq,  wqh, wql, HID * HID / 4);
    cvt_split<<<(HID * HID / 4 + 255) / 256, blk>>>(Wmb, wmh, wml, HID * HID / 4);
    cvt_split<<<(HID * HID / 4 + 255) / 256, blk>>>(Wg,  wgh, wgl, HID * HID / 4);
    cvt_split<<<(512 * HID / 4 + 255) / 256, blk>>>(Wk,  wkh, wkl, 512 * HID / 4);
    cvt_split<<<(512 * HID / 4 + 255) / 256, blk>>>(Wv,  wvh, wvl, 512 * HID / 4);

    // 1) Projections on tensor cores (bf16-split, fp32 accumulate)
    gemm_mma<0><<<dim3(HID / 128, S / 128), blk, MMA_SMEM>>>(xh, xl, wqh, wql, bq,  pQ,  HID, HID);
    gemm_mma<0><<<dim3(512 / 128, S / 128), blk, MMA_SMEM>>>(xh, xl, wkh, wkl, bk,  pK,  512, HID);
    gemm_mma<0><<<dim3(512 / 128, S / 128), blk, MMA_SMEM>>>(xh, xl, wvh, wvl, bv,  pV,  512, HID);
    gemm_mma<1><<<dim3(HID / 128, S / 128), blk, MMA_SMEM>>>(xh, xl, wmh, wml, bmb, pMB, HID, HID);
    gemm_mma<1><<<dim3(HID / 128, S / 128), blk, MMA_SMEM>>>(xh, xl, wgh, wgl, bg,  pG,  HID, HID);

    // 2) dpfp + normalize
    dpfp_kernel<true ><<<dim3(S, NKV), blk>>>(pK, pMK, normv);
    dpfp_kernel<false><<<dim3(S, NH ), blk>>>(pQ, pMQ, nullptr);

    // 3) num = ext_mk @ memory
    gemm_skinny<<<dim3(S / 128, NH), blk>>>(pMK, 4, (size_t)S * FF,
                                            memv, (size_t)FF * DD,
                                            pNUM, (size_t)S * DD, FF);

    // 4) weighted_mv
    wmv_kernel<<<(NH * S * DD) / 256, blk>>>();

    // 5) delta_memory (split-K=4), delta_norm, add
    gemm_delta<<<dim3(FF / 128, 4, NH), blk>>>();
    delta_norm_kernel<<<dim3(FF / 64, NKV), blk>>>(normv, out_norm);
    add_delta_kernel<<<MEM_ELEMS / 256, blk>>>(memv, out_mem);

    // 6) associate
    dena_kernel<<<dim3(S, NH), blk>>>(out_norm);
    gemm_skinny<<<dim3(S / 128, NH), blk>>>(pMQ, 1, (size_t)S * FF,
                                            out_mem, (size_t)FF * DD,
                                            pNUM, (size_t)S * DD, FF);
    final_kernel<<<OUT_ELEMS / 256, blk>>>(X, out);
}

// round 9
// speedup vs baseline: 2.1893x; 1.2422x over previous
#include <cuda_runtime.h>
#include <cuda_bf16.h>
#include <math.h>
#include <stdint.h>

// ---------------- Problem constants ----------------
#define S      4096
#define HID    2048
#define NH     16
#define NKV    4
#define DD     128
#define FF     768
#define EPSV   1e-8f

#define OUT_ELEMS    (S * HID)
#define MEM_ELEMS    (NH * FF * DD)

// ---------------- Scratch (device globals; no allocation allowed) ----------------
__device__ __align__(16) float g_K  [S * 512];
__device__ __align__(16) float g_V  [S * 512];
__device__ __align__(16) float g_Q  [S * HID];
__device__ __align__(16) float g_MB [S * HID];
__device__ __align__(16) float g_G  [S * HID];
__device__ __align__(16) float g_NUM[(size_t)NH * S * DD];
__device__ __align__(16) float g_DELTA[4][(size_t)NH * FF * DD];
__device__ float g_DEN [NH * S];
__device__ float g_COEF[NH * S];
__device__ float g_DENA[NH * S];

// bf16 split operands
__device__ __align__(16) __nv_bfloat16 g_XH [S * HID];
__device__ __align__(16) __nv_bfloat16 g_XL [S * HID];
__device__ __align__(16) __nv_bfloat16 g_WqH[HID * HID], g_WqL[HID * HID];
__device__ __align__(16) __nv_bfloat16 g_WmH[HID * HID], g_WmL[HID * HID];
__device__ __align__(16) __nv_bfloat16 g_WgH[HID * HID], g_WgL[HID * HID];
__device__ __align__(16) __nv_bfloat16 g_WkH[512 * HID], g_WkL[512 * HID];
__device__ __align__(16) __nv_bfloat16 g_WvH[512 * HID], g_WvL[512 * HID];
__device__ __align__(16) __nv_bfloat16 g_MKH[(size_t)NKV * S * FF], g_MKL[(size_t)NKV * S * FF];
__device__ __align__(16) __nv_bfloat16 g_MQH[(size_t)NH * S * FF], g_MQL[(size_t)NH * S * FF];
__device__ __align__(16) __nv_bfloat16 g_MemH[MEM_ELEMS],  g_MemL[MEM_ELEMS];
__device__ __align__(16) __nv_bfloat16 g_NMemH[MEM_ELEMS], g_NMemL[MEM_ELEMS];
__device__ __align__(16) __nv_bfloat16 g_WMVH[(size_t)NH * S * DD], g_WMVL[(size_t)NH * S * DD];

// ---------------- helpers ----------------
__device__ __forceinline__ float warp_sum(float v) {
#pragma unroll
    for (int o = 16; o > 0; o >>= 1) v += __shfl_down_sync(0xffffffffu, v, o);
    return v;
}
__device__ __forceinline__ uint32_t smem_u32(const void* p) {
    uint32_t a;
    asm("{ .reg .u64 t; cvta.to.shared.u64 t, %1; cvt.u32.u64 %0, t; }"
        : "=r"(a) : "l"(p));
    return a;
}
__device__ __forceinline__ void cp_async16(uint32_t sa, const void* g) {
    asm volatile("cp.async.cg.shared.global [%0], [%1], 16;" :: "r"(sa), "l"(g) : "memory");
}
__device__ __forceinline__ void cp_commit() {
    asm volatile("cp.async.commit_group;" ::: "memory");
}
template<int N> __device__ __forceinline__ void cp_wait() {
    asm volatile("cp.async.wait_group %0;" :: "n"(N) : "memory");
}
__device__ __forceinline__ void ldm_x4(uint32_t* r, uint32_t addr) {
    asm volatile("ldmatrix.sync.aligned.m8n8.x4.shared.b16 {%0,%1,%2,%3}, [%4];"
                 : "=r"(r[0]), "=r"(r[1]), "=r"(r[2]), "=r"(r[3]) : "r"(addr));
}
__device__ __forceinline__ void ldm_x2(uint32_t* r, uint32_t addr) {
    asm volatile("ldmatrix.sync.aligned.m8n8.x2.shared.b16 {%0,%1}, [%2];"
                 : "=r"(r[0]), "=r"(r[1]) : "r"(addr));
}
__device__ __forceinline__ void ldm_x4_t(uint32_t* r, uint32_t addr) {
    asm volatile("ldmatrix.sync.aligned.m8n8.x4.trans.shared.b16 {%0,%1,%2,%3}, [%4];"
                 : "=r"(r[0]), "=r"(r[1]), "=r"(r[2]), "=r"(r[3]) : "r"(addr));
}
__device__ __forceinline__ void ldm_x2_t(uint32_t* r, uint32_t addr) {
    asm volatile("ldmatrix.sync.aligned.m8n8.x2.trans.shared.b16 {%0,%1}, [%2];"
                 : "=r"(r[0]), "=r"(r[1]) : "r"(addr));
}
__device__ __forceinline__ void mma_bf16(float* c, const uint32_t* a, const uint32_t* b) {
    asm volatile(
        "mma.sync.aligned.m16n8k16.row.col.f32.bf16.bf16.f32 "
        "{%0,%1,%2,%3}, {%4,%5,%6,%7}, {%8,%9}, {%0,%1,%2,%3};"
        : "+f"(c[0]), "+f"(c[1]), "+f"(c[2]), "+f"(c[3])
        : "r"(a[0]), "r"(a[1]), "r"(a[2]), "r"(a[3]), "r"(b[0]), "r"(b[1]));
}
__device__ __forceinline__ void split_write(float v, __nv_bfloat16* hp, __nv_bfloat16* lp,
                                            size_t idx) {
    __nv_bfloat16 h = __float2bfloat16(v);
    hp[idx] = h;
    lp[idx] = __float2bfloat16(v - __bfloat162float(h));
}

// ======================================================================
// fp32 -> bf16 hi/lo split conversion (vectorized x4)
// ======================================================================
__global__ void cvt_split(const float* __restrict__ x,
                          __nv_bfloat16* __restrict__ hi,
                          __nv_bfloat16* __restrict__ lo, int n4)
{
    int i = blockIdx.x * 256 + threadIdx.x;
    if (i >= n4) return;
    float4 v = ((const float4*)x)[i];
    __nv_bfloat16 h0 = __float2bfloat16(v.x), h1 = __float2bfloat16(v.y);
    __nv_bfloat16 h2 = __float2bfloat16(v.z), h3 = __float2bfloat16(v.w);
    __nv_bfloat16 l0 = __float2bfloat16(v.x - __bfloat162float(h0));
    __nv_bfloat16 l1 = __float2bfloat16(v.y - __bfloat162float(h1));
    __nv_bfloat16 l2 = __float2bfloat16(v.z - __bfloat162float(h2));
    __nv_bfloat16 l3 = __float2bfloat16(v.w - __bfloat162float(h3));
    __nv_bfloat162* hp = (__nv_bfloat162*)hi;
    __nv_bfloat162* lp = (__nv_bfloat162*)lo;
    hp[2 * i]     = __nv_bfloat162(h0, h1);
    hp[2 * i + 1] = __nv_bfloat162(h2, h3);
    lp[2 * i]     = __nv_bfloat162(l0, l1);
    lp[2 * i + 1] = __nv_bfloat162(l2, l3);
}

// ======================================================================
// Projection GEMM (bf16-split mma.sync): C = A @ W^T + bias (opt sigmoid)
// ======================================================================
#define MMA_TILE_B   10240              // 128 rows * 80 bytes
#define MMA_STAGE_B  (4 * MMA_TILE_B)
#define MMA_SMEM     (2 * MMA_STAGE_B)

template <int ACT>
__global__ __launch_bounds__(256, 1) void gemm_mma(
    const __nv_bfloat16* __restrict__ Ahi, const __nv_bfloat16* __restrict__ Alo,
    const __nv_bfloat16* __restrict__ Bhi, const __nv_bfloat16* __restrict__ Blo,
    const float* __restrict__ bias, float* __restrict__ C, int N, int K)
{
    extern __shared__ char sm[];
    const int tid  = threadIdx.x;
    const int lane = tid & 31;
    const int warp = tid >> 5;
    const int wm = warp >> 2;
    const int wn = warp & 3;
    const int bm = blockIdx.y * 128;
    const int bn = blockIdx.x * 128;
    const uint32_t sbase = smem_u32(sm);

    const __nv_bfloat16* srcs[4] = {Ahi, Alo, Bhi, Blo};
    const int rb4[4] = {bm, bm, bn, bn};

    auto load_chunk = [&](int c, int st) {
        const int k0 = c << 5;
        const uint32_t stb = sbase + (uint32_t)st * MMA_STAGE_B;
#pragma unroll
        for (int tile = 0; tile < 4; ++tile) {
            const __nv_bfloat16* src = srcs[tile] + (size_t)rb4[tile] * K + k0;
#pragma unroll
            for (int rep = 0; rep < 2; ++rep) {
                int i = tid + rep * 256;
                int r = i >> 2, cc = i & 3;
                cp_async16(stb + (uint32_t)tile * MMA_TILE_B + r * 80 + cc * 16,
                           src + (size_t)r * K + cc * 8);
            }
        }
        cp_commit();
    };

    float acc[4][4][4];
#pragma unroll
    for (int mt = 0; mt < 4; ++mt)
#pragma unroll
        for (int nt = 0; nt < 4; ++nt)
#pragma unroll
            for (int r = 0; r < 4; ++r) acc[mt][nt][r] = 0.f;

    const int NC = K >> 5;
    load_chunk(0, 0);

    for (int c = 0; c < NC; ++c) {
        const int st = c & 1;
        if (c + 1 < NC) { load_chunk(c + 1, st ^ 1); cp_wait<1>(); }
        else            { cp_wait<0>(); }
        __syncthreads();

        const uint32_t stb = sbase + (uint32_t)st * MMA_STAGE_B;
#pragma unroll
        for (int k16 = 0; k16 < 2; ++k16) {
            uint32_t ah[4][4], al[4][4];
#pragma unroll
            for (int mt = 0; mt < 4; ++mt) {
                uint32_t rowa = (uint32_t)(wm * 64 + mt * 16 + (lane & 15));
                uint32_t coff = (uint32_t)((k16 * 16 + ((lane >> 4) << 3)) * 2);
                ldm_x4(ah[mt], stb + 0 * MMA_TILE_B + rowa * 80 + coff);
                ldm_x4(al[mt], stb + 1 * MMA_TILE_B + rowa * 80 + coff);
            }
#pragma unroll
            for (int nt = 0; nt < 4; ++nt) {
                uint32_t rowb = (uint32_t)(wn * 32 + nt * 8 + (lane & 7));
                uint32_t coff = (uint32_t)((k16 * 16 + (((lane >> 3) & 1) << 3)) * 2);
                uint32_t bh[2], bl[2];
                ldm_x2(bh, stb + 2 * MMA_TILE_B + rowb * 80 + coff);
                ldm_x2(bl, stb + 3 * MMA_TILE_B + rowb * 80 + coff);
#pragma unroll
                for (int mt = 0; mt < 4; ++mt) {
                    mma_bf16(acc[mt][nt], ah[mt], bh);
                    mma_bf16(acc[mt][nt], ah[mt], bl);
                    mma_bf16(acc[mt][nt], al[mt], bh);
                }
            }
        }
        __syncthreads();
    }

    const int r0 = bm + wm * 64;
    const int c0 = bn + wn * 32;
    const int rl = lane >> 2;
    const int cl = (lane & 3) * 2;
#pragma unroll
    for (int mt = 0; mt < 4; ++mt) {
#pragma unroll
        for (int nt = 0; nt < 4; ++nt) {
            int col = c0 + nt * 8 + cl;
            float b0 = bias[col], b1 = bias[col + 1];
#pragma unroll
            for (int half = 0; half < 2; ++half) {
                int row = r0 + mt * 16 + rl + half * 8;
                float v0 = acc[mt][nt][2 * half + 0] + b0;
                float v1 = acc[mt][nt][2 * half + 1] + b1;
                if (ACT) {
                    v0 = 1.f / (1.f + expf(-v0));
                    v1 = 1.f / (1.f + expf(-v1));
                }
                *(float2*)(C + (size_t)row * N + col) = make_float2(v0, v1);
            }
        }
    }
}

// ======================================================================
// Skinny einsum GEMM on tensor cores (bf16-split):
// per head h: C[h][M=4096 tile,128] = A[h/adiv][M,768] @ B[h][768,128]
// A row-major K-contig (non-trans ldmatrix); B row-major N-contig (trans).
// grid = (32, NH). Padded strides: A 80B, B 272B.
// ======================================================================
#define SK_AT_B 10240                 // A tile: 128 x 80B
#define SK_BT_B 8704                  // B tile: 32 x 272B
#define SK_STAGE (2*SK_AT_B + 2*SK_BT_B)   // 37888
#define SK_SMEM  (2 * SK_STAGE)            // 75776

__global__ __launch_bounds__(256, 1) void gemm_skinny_mma(
    const __nv_bfloat16* __restrict__ AH, const __nv_bfloat16* __restrict__ AL,
    int adiv,
    const __nv_bfloat16* __restrict__ BH, const __nv_bfloat16* __restrict__ BL,
    float* __restrict__ Cbase)
{
    extern __shared__ char sm[];
    const int tid  = threadIdx.x;
    const int lane = tid & 31;
    const int warp = tid >> 5;
    const int wm = warp >> 2;
    const int wn = warp & 3;
    const int h  = blockIdx.y;
    const int bm = blockIdx.x * 128;
    const uint32_t sbase = smem_u32(sm);

    const __nv_bfloat16* Ah = AH + (size_t)(h / adiv) * S * FF;
    const __nv_bfloat16* Al = AL + (size_t)(h / adiv) * S * FF;
    const __nv_bfloat16* Bh = BH + (size_t)h * FF * DD;
    const __nv_bfloat16* Bl = BL + (size_t)h * FF * DD;
    float* C = Cbase + (size_t)h * S * DD;

    auto load_chunk = [&](int c, int st) {
        const int k0 = c << 5;
        const uint32_t stb = sbase + (uint32_t)st * SK_STAGE;
        const __nv_bfloat16* asrc[2] = {Ah, Al};
        const __nv_bfloat16* bsrc[2] = {Bh, Bl};
#pragma unroll
        for (int half = 0; half < 2; ++half) {
            // A tile: 128 rows x 32 cols
#pragma unroll
            for (int rep = 0; rep < 2; ++rep) {
                int i = tid + rep * 256;
                int r = i >> 2, cc = i & 3;
                cp_async16(stb + (uint32_t)half * SK_AT_B + r * 80 + cc * 16,
                           asrc[half] + (size_t)(bm + r) * FF + k0 + cc * 8);
            }
            // B tile: 32 rows x 128 cols
#pragma unroll
            for (int rep = 0; rep < 2; ++rep) {
                int i = tid + rep * 256;
                int r = i >> 4, cc = i & 15;
                cp_async16(stb + 2 * SK_AT_B + (uint32_t)half * SK_BT_B + r * 272 + cc * 16,
                           bsrc[half] + (size_t)(k0 + r) * DD + cc * 8);
            }
        }
        cp_commit();
    };

    float acc[4][4][4];
#pragma unroll
    for (int mt = 0; mt < 4; ++mt)
#pragma unroll
        for (int nt = 0; nt < 4; ++nt)
#pragma unroll
            for (int r = 0; r < 4; ++r) acc[mt][nt][r] = 0.f;

    const int NC = FF >> 5;   // 24
    load_chunk(0, 0);

    for (int c = 0; c < NC; ++c) {
        const int st = c & 1;
        if (c + 1 < NC) { load_chunk(c + 1, st ^ 1); cp_wait<1>(); }
        else            { cp_wait<0>(); }
        __syncthreads();

        const uint32_t stb = sbase + (uint32_t)st * SK_STAGE;
#pragma unroll
        for (int k16 = 0; k16 < 2; ++k16) {
            uint32_t ah[4][4], al[4][4];
#pragma unroll
            for (int mt = 0; mt < 4; ++mt) {
                uint32_t rowa = (uint32_t)(wm * 64 + mt * 16 + (lane & 15));
                uint32_t coff = (uint32_t)((k16 * 16 + ((lane >> 4) << 3)) * 2);
                ldm_x4(ah[mt], stb + 0 * SK_AT_B + rowa * 80 + coff);
                ldm_x4(al[mt], stb + 1 * SK_AT_B + rowa * 80 + coff);
            }
#pragma unroll
            for (int nt = 0; nt < 4; ++nt) {
                uint32_t rowb = (uint32_t)(k16 * 16 + (lane & 15));
                uint32_t noff = (uint32_t)((wn * 32 + nt * 8) * 2);
                uint32_t bh[2], bl[2];
                ldm_x2_t(bh, stb + 2 * SK_AT_B + 0 * SK_BT_B + rowb * 272 + noff);
                ldm_x2_t(bl, stb + 2 * SK_AT_B + 1 * SK_BT_B + rowb * 272 + noff);
#pragma unroll
                for (int mt = 0; mt < 4; ++mt) {
                    mma_bf16(acc[mt][nt], ah[mt], bh);
                    mma_bf16(acc[mt][nt], ah[mt], bl);
                    mma_bf16(acc[mt][nt], al[mt], bh);
                }
            }
        }
        __syncthreads();
    }

    const int r0 = bm + wm * 64;
    const int c0 = wn * 32;
    const int rl = lane >> 2;
    const int cl = (lane & 3) * 2;
#pragma unroll
    for (int mt = 0; mt < 4; ++mt)
#pragma unroll
        for (int nt = 0; nt < 4; ++nt) {
            int col = c0 + nt * 8 + cl;
#pragma unroll
            for (int half = 0; half < 2; ++half) {
                int row = r0 + mt * 16 + rl + half * 8;
                *(float2*)(C + (size_t)row * DD + col) =
                    make_float2(acc[mt][nt][2 * half], acc[mt][nt][2 * half + 1]);
            }
        }
}

// ======================================================================
// Delta GEMM on tensor cores (bf16-split, split-K=4):
// DELTA[part][h][f,d] = sum_{s in part} MK[h/4][s,f] * WMV[h][s,d]
// Both operands [s][col] -> trans ldmatrix for A and B.
// grid = (6, 4, 16).
// ======================================================================
#define DL_T_B 8704                   // 32 x 272B
#define DL_STAGE (4 * DL_T_B)         // 34816
#define DL_SMEM  (2 * DL_STAGE)       // 69632

__global__ __launch_bounds__(256, 1) void gemm_delta_mma()
{
    extern __shared__ char sm[];
    const int tid  = threadIdx.x;
    const int lane = tid & 31;
    const int warp = tid >> 5;
    const int wm = warp >> 2;
    const int wn = warp & 3;
    const int h    = blockIdx.z;
    const int part = blockIdx.y;
    const int f0   = blockIdx.x * 128;
    const uint32_t sbase = smem_u32(sm);

    const __nv_bfloat16* Ah = g_MKH + (size_t)(h >> 2) * S * FF;
    const __nv_bfloat16* Al = g_MKL + (size_t)(h >> 2) * S * FF;
    const __nv_bfloat16* Bh = g_WMVH + (size_t)h * S * DD;
    const __nv_bfloat16* Bl = g_WMVL + (size_t)h * S * DD;

    const int kbase = part * (S / 4);

    auto load_chunk = [&](int c, int st) {
        const int k0 = kbase + (c << 5);
        const uint32_t stb = sbase + (uint32_t)st * DL_STAGE;
        const __nv_bfloat16* srcs[4] = {Ah, Al, Bh, Bl};
#pragma unroll
        for (int tile = 0; tile < 4; ++tile) {
            const bool isA = tile < 2;
#pragma unroll
            for (int rep = 0; rep < 2; ++rep) {
                int i = tid + rep * 256;
                int r = i >> 4, cc = i & 15;
                const __nv_bfloat16* src = isA
                    ? srcs[tile] + (size_t)(k0 + r) * FF + f0 + cc * 8
                    : srcs[tile] + (size_t)(k0 + r) * DD + cc * 8;
                cp_async16(stb + (uint32_t)tile * DL_T_B + r * 272 + cc * 16, src);
            }
        }
        cp_commit();
    };

    float acc[4][4][4];
#pragma unroll
    for (int mt = 0; mt < 4; ++mt)
#pragma unroll
        for (int nt = 0; nt < 4; ++nt)
#pragma unroll
            for (int r = 0; r < 4; ++r) acc[mt][nt][r] = 0.f;

    const int NC = (S / 4) >> 5;   // 32
    load_chunk(0, 0);

    for (int c = 0; c < NC; ++c) {
        const int st = c & 1;
        if (c + 1 < NC) { load_chunk(c + 1, st ^ 1); cp_wait<1>(); }
        else            { cp_wait<0>(); }
        __syncthreads();

        const uint32_t stb = sbase + (uint32_t)st * DL_STAGE;
#pragma unroll
        for (int k16 = 0; k16 < 2; ++k16) {
            uint32_t ah[4][4], al[4][4];
            // A trans: row = k (s), col = m (f)
            uint32_t rowa = (uint32_t)(k16 * 16 + (lane & 7) + ((lane >> 4) << 3));
#pragma unroll
            for (int mt = 0; mt < 4; ++mt) {
                uint32_t cola = (uint32_t)((wm * 64 + mt * 16 + (((lane >> 3) & 1) << 3)) * 2);
                ldm_x4_t(ah[mt], stb + 0 * DL_T_B + rowa * 272 + cola);
                ldm_x4_t(al[mt], stb + 1 * DL_T_B + rowa * 272 + cola);
            }
#pragma unroll
            for (int nt = 0; nt < 4; ++nt) {
                uint32_t rowb = (uint32_t)(k16 * 16 + (lane & 15));
                uint32_t noff = (uint32_t)((wn * 32 + nt * 8) * 2);
                uint32_t bh[2], bl[2];
                ldm_x2_t(bh, stb + 2 * DL_T_B + rowb * 272 + noff);
                ldm_x2_t(bl, stb + 3 * DL_T_B + rowb * 272 + noff);
#pragma unroll
                for (int mt = 0; mt < 4; ++mt) {
                    mma_bf16(acc[mt][nt], ah[mt], bh);
                    mma_bf16(acc[mt][nt], ah[mt], bl);
                    mma_bf16(acc[mt][nt], al[mt], bh);
                }
            }
        }
        __syncthreads();
    }

    float* Cp = g_DELTA[part] + (size_t)h * FF * DD;
    const int r0 = f0 + wm * 64;
    const int c0 = wn * 32;
    const int rl = lane >> 2;
    const int cl = (lane & 3) * 2;
#pragma unroll
    for (int mt = 0; mt < 4; ++mt)
#pragma unroll
        for (int nt = 0; nt < 4; ++nt) {
            int col = c0 + nt * 8 + cl;
#pragma unroll
            for (int half = 0; half < 2; ++half) {
                int row = r0 + mt * 16 + rl + half * 8;
                *(float2*)(Cp + (size_t)row * DD + col) =
                    make_float2(acc[mt][nt][2 * half], acc[mt][nt][2 * half + 1]);
            }
        }
}

// ======================================================================
// dpfp + L2-normalize, emits bf16 hi/lo. K variant fuses denom/coef.
// ======================================================================
template <bool WITHDEN>
__global__ __launch_bounds__(256) void dpfp_kernel(
    const float* __restrict__ X,
    __nv_bfloat16* __restrict__ outh, __nv_bfloat16* __restrict__ outl,
    const float* __restrict__ normv)
{
    const int s  = blockIdx.x;
    const int hh = blockIdx.y;
    const int nh = gridDim.y;
    const int t  = threadIdx.x;
    __shared__ float y[256];
    __shared__ float red[5][8];

    const float* x = X + ((size_t)s * nh + hh) * 128;
    float xv = (t < 128) ? x[t] : -x[t - 128];
    y[t] = fmaxf(xv, 0.f);
    __syncthreads();

    float yi = y[t];
    float m0 = yi * y[(t - 1) & 255];
    float m1 = yi * y[(t - 2) & 255];
    float m2 = yi * y[(t - 3) & 255];
    float ss = m0 * m0 + m1 * m1 + m2 * m2;

    float dd[4];
    if (WITHDEN) {
#pragma unroll
        for (int g = 0; g < 4; g++) {
            const float* nr = normv + (size_t)(4 * hh + g) * FF;
            dd[g] = m0 * nr[t] + m1 * nr[256 + t] + m2 * nr[512 + t];
        }
    }

    const int lane = t & 31, w = t >> 5;
    float r0 = warp_sum(ss);
    if (lane == 0) red[0][w] = r0;
    if (WITHDEN) {
#pragma unroll
        for (int g = 0; g < 4; g++) {
            float rg = warp_sum(dd[g]);
            if (lane == 0) red[1 + g][w] = rg;
        }
    }
    __syncthreads();

    float ssT = 0.f;
#pragma unroll
    for (int w2 = 0; w2 < 8; w2++) ssT += red[0][w2];
    float nrm = sqrtf(ssT);
    float inv = 1.f / fmaxf(nrm, 1e-12f);

    size_t base = ((size_t)hh * S + s) * FF;
    split_write(m0 * inv, outh, outl, base + t);
    split_write(m1 * inv, outh, outl, base + 256 + t);
    split_write(m2 * inv, outh, outl, base + 512 + t);

    if (WITHDEN && t < 4) {
        float dT = 0.f;
#pragma unroll
        for (int w2 = 0; w2 < 8; w2++) dT += red[1 + t][w2];
        float den  = dT * inv + EPSV;
        float mksq = ssT * inv * inv;
        float coef = 1.f - den / mksq;
        coef = fminf(fmaxf(coef, 0.f), 1.f);
        int h = 4 * hh + t;
        g_DEN[h * S + s]  = den;
        g_COEF[h * S + s] = coef;
    }
}

// weighted_mv = (v - num/denom) * mb -> bf16 hi/lo
__global__ void wmv_kernel()
{
    size_t idx = (size_t)blockIdx.x * 256 + threadIdx.x;
    int h = (int)(idx >> 19);
    size_t r = idx & ((1u << 19) - 1);
    int s  = (int)(r >> 7);
    int d0 = (int)(r & 127);
    float den  = g_DEN[h * S + s];
    float prev = g_NUM[idx] / den;
    float v  = g_V[(size_t)s * 512 + (size_t)(h >> 2) * 128 + d0];
    float mb = g_MB[(size_t)s * HID + (size_t)h * 128 + d0];
    split_write((v - prev) * mb, g_WMVH, g_WMVL, idx);
}

// new_norm[h][f] = norm[h][f] + sum_s coef[h][s]*MK[h/4][s][f]   (MK = hi+lo)
__global__ __launch_bounds__(256) void delta_norm_kernel(
    const float* __restrict__ normv, float* __restrict__ out_norm)
{
    const int kv = blockIdx.y;
    const int f0 = blockIdx.x * 64;
    const int t  = threadIdx.x;
    const int fl = t & 63, sl = t >> 6;

    float acc[4] = {0.f, 0.f, 0.f, 0.f};
    const __nv_bfloat16* mh = g_MKH + (size_t)kv * S * FF + f0 + fl;
    const __nv_bfloat16* ml = g_MKL + (size_t)kv * S * FF + f0 + fl;
    for (int s = sl; s < S; s += 4) {
        float v = __bfloat162float(mh[(size_t)s * FF]) + __bfloat162float(ml[(size_t)s * FF]);
#pragma unroll
        for (int g = 0; g < 4; g++)
            acc[g] = fmaf(g_COEF[(4 * kv + g) * S + s], v, acc[g]);
    }
    __shared__ float smr[4][4][64];
#pragma unroll
    for (int g = 0; g < 4; g++) smr[sl][g][fl] = acc[g];
    __syncthreads();
    if (t < 64) {
#pragma unroll
        for (int g = 0; g < 4; g++) {
            float sum = smr[0][g][t] + smr[1][g][t] + smr[2][g][t] + smr[3][g][t];
            int h = 4 * kv + g;
            out_norm[(size_t)h * FF + f0 + t] = normv[(size_t)h * FF + f0 + t] + sum;
        }
    }
}

// new_memory = memory + sum partials; also emit hi/lo bf16
__global__ void add_delta_kernel(const float* __restrict__ memory,
                                 float* __restrict__ out_mem)
{
    size_t idx = (size_t)blockIdx.x * 256 + threadIdx.x;
    float v = memory[idx] + g_DELTA[0][idx] + g_DELTA[1][idx]
            + g_DELTA[2][idx] + g_DELTA[3][idx];
    out_mem[idx] = v;
    split_write(v, g_NMemH, g_NMemL, idx);
}

// den_a[h,s] = dot(mq, new_norm[h]) + EPS   (mq = hi+lo)
__global__ __launch_bounds__(256) void dena_kernel(const float* __restrict__ newnorm)
{
    const int s = blockIdx.x, h = blockIdx.y;
    const int t = threadIdx.x;
    const __nv_bfloat16* qh = g_MQH + ((size_t)h * S + s) * FF;
    const __nv_bfloat16* ql = g_MQL + ((size_t)h * S + s) * FF;
    const float* nr = newnorm + (size_t)h * FF;
    float dd = 0.f;
#pragma unroll
    for (int j = 0; j < 3; j++) {
        int i = j * 256 + t;
        float mq = __bfloat162float(qh[i]) + __bfloat162float(ql[i]);
        dd = fmaf(mq, nr[i], dd);
    }
    __shared__ float red[8];
    float r = warp_sum(dd);
    if ((t & 31) == 0) red[t >> 5] = r;
    __syncthreads();
    if (t == 0) {
        float s8 = 0.f;
#pragma unroll
        for (int w = 0; w < 8; w++) s8 += red[w];
        g_DENA[h * S + s] = s8 + EPSV;
    }
}

__global__ void final_kernel(const float* __restrict__ X, float* __restrict__ out)
{
    size_t idx = (size_t)blockIdx.x * 256 + threadIdx.x;
    int s  = (int)(idx >> 11);
    int c  = (int)(idx & 2047);
    int h  = c >> 7;
    int d0 = c & 127;
    float numa = g_NUM[((size_t)h * S + s) * DD + d0];
    float mh = numa / g_DENA[h * S + s];
    out[idx] = X[idx] + g_G[idx] * mh;
}

// ======================================================================
// Launch
// ======================================================================
extern "C" void kernel_launch(void* const* d_in, const int* in_sizes, int n_in,
                              void* d_out, int out_size)
{
    const float* X    = (const float*)d_in[0];
    const float* Wq   = (const float*)d_in[1];
    const float* bq   = (const float*)d_in[2];
    const float* Wk   = (const float*)d_in[3];
    const float* bk   = (const float*)d_in[4];
    const float* Wv   = (const float*)d_in[5];
    const float* bv   = (const float*)d_in[6];
    const float* Wg   = (const float*)d_in[7];
    const float* bg   = (const float*)d_in[8];
    const float* Wmb  = (const float*)d_in[9];
    const float* bmb  = (const float*)d_in[10];
    const float* memv = (const float*)d_in[11];
    const float* normv= (const float*)d_in[12];

    float* out      = (float*)d_out;
    float* out_mem  = out + OUT_ELEMS;
    float* out_norm = out_mem + MEM_ELEMS;

    float *pK, *pV, *pQ, *pMB, *pG, *pNUM;
    cudaGetSymbolAddress((void**)&pK,  g_K);
    cudaGetSymbolAddress((void**)&pV,  g_V);
    cudaGetSymbolAddress((void**)&pQ,  g_Q);
    cudaGetSymbolAddress((void**)&pMB, g_MB);
    cudaGetSymbolAddress((void**)&pG,  g_G);
    cudaGetSymbolAddress((void**)&pNUM, g_NUM);

    __nv_bfloat16 *xh, *xl, *wqh, *wql, *wmh, *wml, *wgh, *wgl, *wkh, *wkl, *wvh, *wvl;
    __nv_bfloat16 *mkh, *mkl, *mqh, *mql, *memh, *meml, *nmh, *nml;
    cudaGetSymbolAddress((void**)&xh,  g_XH);  cudaGetSymbolAddress((void**)&xl,  g_XL);
    cudaGetSymbolAddress((void**)&wqh, g_WqH); cudaGetSymbolAddress((void**)&wql, g_WqL);
    cudaGetSymbolAddress((void**)&wmh, g_WmH); cudaGetSymbolAddress((void**)&wml, g_WmL);
    cudaGetSymbolAddress((void**)&wgh, g_WgH); cudaGetSymbolAddress((void**)&wgl, g_WgL);
    cudaGetSymbolAddress((void**)&wkh, g_WkH); cudaGetSymbolAddress((void**)&wkl, g_WkL);
    cudaGetSymbolAddress((void**)&wvh, g_WvH); cudaGetSymbolAddress((void**)&wvl, g_WvL);
    cudaGetSymbolAddress((void**)&mkh, g_MKH); cudaGetSymbolAddress((void**)&mkl, g_MKL);
    cudaGetSymbolAddress((void**)&mqh, g_MQH); cudaGetSymbolAddress((void**)&mql, g_MQL);
    cudaGetSymbolAddress((void**)&memh, g_MemH); cudaGetSymbolAddress((void**)&meml, g_MemL);
    cudaGetSymbolAddress((void**)&nmh, g_NMemH); cudaGetSymbolAddress((void**)&nml, g_NMemL);

    cudaFuncSetAttribute(gemm_mma<0>, cudaFuncAttributeMaxDynamicSharedMemorySize, MMA_SMEM);
    cudaFuncSetAttribute(gemm_mma<1>, cudaFuncAttributeMaxDynamicSharedMemorySize, MMA_SMEM);
    cudaFuncSetAttribute(gemm_skinny_mma, cudaFuncAttributeMaxDynamicSharedMemorySize, SK_SMEM);
    cudaFuncSetAttribute(gemm_delta_mma, cudaFuncAttributeMaxDynamicSharedMemorySize, DL_SMEM);

    dim3 blk(256);

    // 0) fp32 -> bf16 hi/lo splits
    cvt_split<<<(S * HID / 4 + 255) / 256, blk>>>(X,   xh,  xl,  S * HID / 4);
    cvt_split<<<(HID * HID / 4 + 255) / 256, blk>>>(Wq,  wqh, wql, HID * HID / 4);
    cvt_split<<<(HID * HID / 4 + 255) / 256, blk>>>(Wmb, wmh, wml, HID * HID / 4);
    cvt_split<<<(HID * HID / 4 + 255) / 256, blk>>>(Wg,  wgh, wgl, HID * HID / 4);
    cvt_split<<<(512 * HID / 4 + 255) / 256, blk>>>(Wk,  wkh, wkl, 512 * HID / 4);
    cvt_split<<<(512 * HID / 4 + 255) / 256, blk>>>(Wv,  wvh, wvl, 512 * HID / 4);
    cvt_split<<<(MEM_ELEMS / 4 + 255) / 256, blk>>>(memv, memh, meml, MEM_ELEMS / 4);

    // 1) Projections on tensor cores
    gemm_mma<0><<<dim3(HID / 128, S / 128), blk, MMA_SMEM>>>(xh, xl, wqh, wql, bq,  pQ,  HID, HID);
    gemm_mma<0><<<dim3(512 / 128, S / 128), blk, MMA_SMEM>>>(xh, xl, wkh, wkl, bk,  pK,  512, HID);
    gemm_mma<0><<<dim3(512 / 128, S / 128), blk, MMA_SMEM>>>(xh, xl, wvh, wvl, bv,  pV,  512, HID);
    gemm_mma<1><<<dim3(HID / 128, S / 128), blk, MMA_SMEM>>>(xh, xl, wmh, wml, bmb, pMB, HID, HID);
    gemm_mma<1><<<dim3(HID / 128, S / 128), blk, MMA_SMEM>>>(xh, xl, wgh, wgl, bg,  pG,  HID, HID);

    // 2) dpfp + normalize (bf16 hi/lo outputs)
    dpfp_kernel<true ><<<dim3(S, NKV), blk>>>(pK, mkh, mkl, normv);
    dpfp_kernel<false><<<dim3(S, NH ), blk>>>(pQ, mqh, mql, nullptr);

    // 3) num = ext_mk @ memory (tensor cores)
    gemm_skinny_mma<<<dim3(S / 128, NH), blk, SK_SMEM>>>(mkh, mkl, 4, memh, meml, pNUM);

    // 4) weighted_mv (bf16 hi/lo out)
    wmv_kernel<<<(NH * S * DD) / 256, blk>>>();

    // 5) delta_memory (tensor cores, split-K=4), delta_norm, add
    gemm_delta_mma<<<dim3(FF / 128, 4, NH), blk, DL_SMEM>>>();
    delta_norm_kernel<<<dim3(FF / 64, NKV), blk>>>(normv, out_norm);
    add_delta_kernel<<<MEM_ELEMS / 256, blk>>>(memv, out_mem);

    // 6) associate
    dena_kernel<<<dim3(S, NH), blk>>>(out_norm);
    gemm_skinny_mma<<<dim3(S / 128, NH), blk, SK_SMEM>>>(mqh, mql, 1, nmh, nml, pNUM);
    final_kernel<<<OUT_ELEMS / 256, blk>>>(X, out);
}

// round 10
// speedup vs baseline: 2.3245x; 1.0617x over previous
#include <cuda_runtime.h>
#include <cuda_bf16.h>
#include <math.h>
#include <stdint.h>

// ---------------- Problem constants ----------------
#define S      4096
#define HID    2048
#define NH     16
#define NKV    4
#define DD     128
#define FF     768
#define EPSV   1e-8f

#define OUT_ELEMS    (S * HID)
#define MEM_ELEMS    (NH * FF * DD)

// ---------------- Scratch (device globals; no allocation allowed) ----------------
__device__ __align__(16) float g_K  [S * 512];
__device__ __align__(16) float g_V  [S * 512];
__device__ __align__(16) float g_Q  [S * HID];
__device__ __align__(16) float g_MB [S * HID];
__device__ __align__(16) float g_G  [S * HID];
__device__ __align__(16) float g_NUM[(size_t)NH * S * DD];
__device__ __align__(16) float g_DELTA[4][(size_t)NH * FF * DD];
__device__ float g_DEN [NH * S];
__device__ float g_COEF[NH * S];
__device__ float g_DENA[NH * S];

// bf16 split operands
__device__ __align__(16) __nv_bfloat16 g_XH [S * HID];
__device__ __align__(16) __nv_bfloat16 g_XL [S * HID];
__device__ __align__(16) __nv_bfloat16 g_WqH[HID * HID], g_WqL[HID * HID];
__device__ __align__(16) __nv_bfloat16 g_WmH[HID * HID], g_WmL[HID * HID];
__device__ __align__(16) __nv_bfloat16 g_WgH[HID * HID], g_WgL[HID * HID];
__device__ __align__(16) __nv_bfloat16 g_WkH[512 * HID], g_WkL[512 * HID];
__device__ __align__(16) __nv_bfloat16 g_WvH[512 * HID], g_WvL[512 * HID];
__device__ __align__(16) __nv_bfloat16 g_MKH[(size_t)NKV * S * FF], g_MKL[(size_t)NKV * S * FF];
__device__ __align__(16) __nv_bfloat16 g_MQH[(size_t)NH * S * FF], g_MQL[(size_t)NH * S * FF];
__device__ __align__(16) __nv_bfloat16 g_MemH[MEM_ELEMS],  g_MemL[MEM_ELEMS];
__device__ __align__(16) __nv_bfloat16 g_NMemH[MEM_ELEMS], g_NMemL[MEM_ELEMS];
__device__ __align__(16) __nv_bfloat16 g_WMVH[(size_t)NH * S * DD], g_WMVL[(size_t)NH * S * DD];

// ---------------- helpers ----------------
__device__ __forceinline__ float warp_sum(float v) {
#pragma unroll
    for (int o = 16; o > 0; o >>= 1) v += __shfl_down_sync(0xffffffffu, v, o);
    return v;
}
__device__ __forceinline__ uint32_t smem_u32(const void* p) {
    uint32_t a;
    asm("{ .reg .u64 t; cvta.to.shared.u64 t, %1; cvt.u32.u64 %0, t; }"
        : "=r"(a) : "l"(p));
    return a;
}
__device__ __forceinline__ void cp_async16(uint32_t sa, const void* g) {
    asm volatile("cp.async.cg.shared.global [%0], [%1], 16;" :: "r"(sa), "l"(g) : "memory");
}
__device__ __forceinline__ void cp_commit() {
    asm volatile("cp.async.commit_group;" ::: "memory");
}
template<int N> __device__ __forceinline__ void cp_wait() {
    asm volatile("cp.async.wait_group %0;" :: "n"(N) : "memory");
}
__device__ __forceinline__ void ldm_x4(uint32_t* r, uint32_t addr) {
    asm volatile("ldmatrix.sync.aligned.m8n8.x4.shared.b16 {%0,%1,%2,%3}, [%4];"
                 : "=r"(r[0]), "=r"(r[1]), "=r"(r[2]), "=r"(r[3]) : "r"(addr));
}
__device__ __forceinline__ void ldm_x2(uint32_t* r, uint32_t addr) {
    asm volatile("ldmatrix.sync.aligned.m8n8.x2.shared.b16 {%0,%1}, [%2];"
                 : "=r"(r[0]), "=r"(r[1]) : "r"(addr));
}
__device__ __forceinline__ void ldm_x4_t(uint32_t* r, uint32_t addr) {
    asm volatile("ldmatrix.sync.aligned.m8n8.x4.trans.shared.b16 {%0,%1,%2,%3}, [%4];"
                 : "=r"(r[0]), "=r"(r[1]), "=r"(r[2]), "=r"(r[3]) : "r"(addr));
}
__device__ __forceinline__ void ldm_x2_t(uint32_t* r, uint32_t addr) {
    asm volatile("ldmatrix.sync.aligned.m8n8.x2.trans.shared.b16 {%0,%1}, [%2];"
                 : "=r"(r[0]), "=r"(r[1]) : "r"(addr));
}
__device__ __forceinline__ void mma_bf16(float* c, const uint32_t* a, const uint32_t* b) {
    asm volatile(
        "mma.sync.aligned.m16n8k16.row.col.f32.bf16.bf16.f32 "
        "{%0,%1,%2,%3}, {%4,%5,%6,%7}, {%8,%9}, {%0,%1,%2,%3};"
        : "+f"(c[0]), "+f"(c[1]), "+f"(c[2]), "+f"(c[3])
        : "r"(a[0]), "r"(a[1]), "r"(a[2]), "r"(a[3]), "r"(b[0]), "r"(b[1]));
}
__device__ __forceinline__ void split_write(float v, __nv_bfloat16* hp, __nv_bfloat16* lp,
                                            size_t idx) {
    __nv_bfloat16 h = __float2bfloat16(v);
    hp[idx] = h;
    lp[idx] = __float2bfloat16(v - __bfloat162float(h));
}

// ======================================================================
// fp32 -> bf16 hi/lo split conversion (vectorized x4)
// ======================================================================
__global__ void cvt_split(const float* __restrict__ x,
                          __nv_bfloat16* __restrict__ hi,
                          __nv_bfloat16* __restrict__ lo, int n4)
{
    int i = blockIdx.x * 256 + threadIdx.x;
    if (i >= n4) return;
    float4 v = ((const float4*)x)[i];
    __nv_bfloat16 h0 = __float2bfloat16(v.x), h1 = __float2bfloat16(v.y);
    __nv_bfloat16 h2 = __float2bfloat16(v.z), h3 = __float2bfloat16(v.w);
    __nv_bfloat16 l0 = __float2bfloat16(v.x - __bfloat162float(h0));
    __nv_bfloat16 l1 = __float2bfloat16(v.y - __bfloat162float(h1));
    __nv_bfloat16 l2 = __float2bfloat16(v.z - __bfloat162float(h2));
    __nv_bfloat16 l3 = __float2bfloat16(v.w - __bfloat162float(h3));
    __nv_bfloat162* hp = (__nv_bfloat162*)hi;
    __nv_bfloat162* lp = (__nv_bfloat162*)lo;
    hp[2 * i]     = __nv_bfloat162(h0, h1);
    hp[2 * i + 1] = __nv_bfloat162(h2, h3);
    lp[2 * i]     = __nv_bfloat162(l0, l1);
    lp[2 * i + 1] = __nv_bfloat162(l2, l3);
}

// ======================================================================
// Projection GEMM (bf16-split mma.sync): C = A @ W^T + bias (opt sigmoid)
// BM=128, BN template (128 or 256), BK=32, 256 threads, 8 warps (2 x 4),
// warp tile 64 x (BN/4). 3-stage cp.async pipeline, one barrier/chunk.
// ======================================================================
#define PJ_A_T 10240                        // 128 rows * 80B

template <int ACT, int BN>
__global__ __launch_bounds__(256, 1) void gemm_mma(
    const __nv_bfloat16* __restrict__ Ahi, const __nv_bfloat16* __restrict__ Alo,
    const __nv_bfloat16* __restrict__ Bhi, const __nv_bfloat16* __restrict__ Blo,
    const float* __restrict__ bias, float* __restrict__ C, int N, int K)
{
    extern __shared__ char sm[];
    constexpr int NT   = BN / 32;           // nt iterations per warp
    constexpr int B_T  = BN * 80;           // B tile bytes per half
    constexpr int STG  = 2 * PJ_A_T + 2 * B_T;
    const int tid  = threadIdx.x;
    const int lane = tid & 31;
    const int warp = tid >> 5;
    const int wm = warp >> 2;
    const int wn = warp & 3;
    const int bm = blockIdx.y * 128;
    const int bn = blockIdx.x * BN;
    const uint32_t sbase = smem_u32(sm);

    auto load_chunk = [&](int c, int st) {
        const int k0 = c << 5;
        const uint32_t stb = sbase + (uint32_t)st * STG;
#pragma unroll
        for (int half = 0; half < 2; ++half) {
            const __nv_bfloat16* src = (half ? Alo : Ahi) + (size_t)bm * K + k0;
#pragma unroll
            for (int rep = 0; rep < 2; ++rep) {
                int i = tid + rep * 256;
                int r = i >> 2, cc = i & 3;
                cp_async16(stb + (uint32_t)half * PJ_A_T + r * 80 + cc * 16,
                           src + (size_t)r * K + cc * 8);
            }
        }
#pragma unroll
        for (int half = 0; half < 2; ++half) {
            const __nv_bfloat16* src = (half ? Blo : Bhi) + (size_t)bn * K + k0;
#pragma unroll
            for (int rep = 0; rep < BN / 64; ++rep) {
                int i = tid + rep * 256;
                int r = i >> 2, cc = i & 3;
                cp_async16(stb + 2 * PJ_A_T + (uint32_t)half * B_T + r * 80 + cc * 16,
                           src + (size_t)r * K + cc * 8);
            }
        }
        cp_commit();
    };

    float acc[4][NT][4];
#pragma unroll
    for (int mt = 0; mt < 4; ++mt)
#pragma unroll
        for (int nt = 0; nt < NT; ++nt)
#pragma unroll
            for (int r = 0; r < 4; ++r) acc[mt][nt][r] = 0.f;

    const int NC = K >> 5;
    load_chunk(0, 0);
    load_chunk(1, 1);

    for (int c = 0; c < NC; ++c) {
        if (c + 1 < NC) cp_wait<1>(); else cp_wait<0>();
        __syncthreads();
        if (c + 2 < NC) load_chunk(c + 2, (c + 2) % 3);

        const uint32_t stb = sbase + (uint32_t)(c % 3) * STG;
#pragma unroll
        for (int k16 = 0; k16 < 2; ++k16) {
            uint32_t ah[4][4], al[4][4];
#pragma unroll
            for (int mt = 0; mt < 4; ++mt) {
                uint32_t rowa = (uint32_t)(wm * 64 + mt * 16 + (lane & 15));
                uint32_t coff = (uint32_t)((k16 * 16 + ((lane >> 4) << 3)) * 2);
                ldm_x4(ah[mt], stb + 0 * PJ_A_T + rowa * 80 + coff);
                ldm_x4(al[mt], stb + 1 * PJ_A_T + rowa * 80 + coff);
            }
#pragma unroll
            for (int nt = 0; nt < NT; ++nt) {
                uint32_t rowb = (uint32_t)(wn * (BN / 4) + nt * 8 + (lane & 7));
                uint32_t coff = (uint32_t)((k16 * 16 + (((lane >> 3) & 1) << 3)) * 2);
                uint32_t bh[2], bl[2];
                ldm_x2(bh, stb + 2 * PJ_A_T + 0 * B_T + rowb * 80 + coff);
                ldm_x2(bl, stb + 2 * PJ_A_T + 1 * B_T + rowb * 80 + coff);
#pragma unroll
                for (int mt = 0; mt < 4; ++mt) {
                    mma_bf16(acc[mt][nt], ah[mt], bh);
                    mma_bf16(acc[mt][nt], ah[mt], bl);
                    mma_bf16(acc[mt][nt], al[mt], bh);
                }
            }
        }
    }

    const int r0 = bm + wm * 64;
    const int c0 = bn + wn * (BN / 4);
    const int rl = lane >> 2;
    const int cl = (lane & 3) * 2;
#pragma unroll
    for (int mt = 0; mt < 4; ++mt) {
#pragma unroll
        for (int nt = 0; nt < NT; ++nt) {
            int col = c0 + nt * 8 + cl;
            float b0 = bias[col], b1 = bias[col + 1];
#pragma unroll
            for (int half = 0; half < 2; ++half) {
                int row = r0 + mt * 16 + rl + half * 8;
                float v0 = acc[mt][nt][2 * half + 0] + b0;
                float v1 = acc[mt][nt][2 * half + 1] + b1;
                if (ACT) {
                    v0 = 1.f / (1.f + expf(-v0));
                    v1 = 1.f / (1.f + expf(-v1));
                }
                *(float2*)(C + (size_t)row * N + col) = make_float2(v0, v1);
            }
        }
    }
}

#define PJ_SMEM_128 (3 * (2 * PJ_A_T + 2 * 128 * 80))   // 122880
#define PJ_SMEM_256 (3 * (2 * PJ_A_T + 2 * 256 * 80))   // 184320

// ======================================================================
// Skinny einsum GEMM (bf16-split): per head h,
// C[h][tile,128] = A[h/adiv][M,768] @ B[h][768,128].
// 3-stage pipeline. WITHDEN: fuse den_a[s] = dot(mq[s,:], nrm[h,:]) + EPS.
// ======================================================================
#define SK_AT_B 10240                 // A tile: 128 x 80B
#define SK_BT_B 8704                  // B tile: 32 x 272B
#define SK_STAGE (2*SK_AT_B + 2*SK_BT_B)   // 37888
#define SK_SMEM  (3 * SK_STAGE)            // 113664

template <int WITHDEN>
__global__ __launch_bounds__(256, 1) void gemm_skinny_mma(
    const __nv_bfloat16* __restrict__ AH, const __nv_bfloat16* __restrict__ AL,
    int adiv,
    const __nv_bfloat16* __restrict__ BH, const __nv_bfloat16* __restrict__ BL,
    float* __restrict__ Cbase, const float* __restrict__ nrm)
{
    extern __shared__ char sm[];
    const int tid  = threadIdx.x;
    const int lane = tid & 31;
    const int warp = tid >> 5;
    const int wm = warp >> 2;
    const int wn = warp & 3;
    const int h  = blockIdx.y;
    const int bm = blockIdx.x * 128;
    const uint32_t sbase = smem_u32(sm);

    const __nv_bfloat16* Ah = AH + (size_t)(h / adiv) * S * FF;
    const __nv_bfloat16* Al = AL + (size_t)(h / adiv) * S * FF;
    const __nv_bfloat16* Bh = BH + (size_t)h * FF * DD;
    const __nv_bfloat16* Bl = BL + (size_t)h * FF * DD;
    float* C = Cbase + (size_t)h * S * DD;

    auto load_chunk = [&](int c, int st) {
        const int k0 = c << 5;
        const uint32_t stb = sbase + (uint32_t)st * SK_STAGE;
        const __nv_bfloat16* asrc[2] = {Ah, Al};
        const __nv_bfloat16* bsrc[2] = {Bh, Bl};
#pragma unroll
        for (int half = 0; half < 2; ++half) {
#pragma unroll
            for (int rep = 0; rep < 2; ++rep) {
                int i = tid + rep * 256;
                int r = i >> 2, cc = i & 3;
                cp_async16(stb + (uint32_t)half * SK_AT_B + r * 80 + cc * 16,
                           asrc[half] + (size_t)(bm + r) * FF + k0 + cc * 8);
            }
#pragma unroll
            for (int rep = 0; rep < 2; ++rep) {
                int i = tid + rep * 256;
                int r = i >> 4, cc = i & 15;
                cp_async16(stb + 2 * SK_AT_B + (uint32_t)half * SK_BT_B + r * 272 + cc * 16,
                           bsrc[half] + (size_t)(k0 + r) * DD + cc * 8);
            }
        }
        cp_commit();
    };

    float acc[4][4][4];
#pragma unroll
    for (int mt = 0; mt < 4; ++mt)
#pragma unroll
        for (int nt = 0; nt < 4; ++nt)
#pragma unroll
            for (int r = 0; r < 4; ++r) acc[mt][nt][r] = 0.f;

    float den = 0.f;
    const float* nrh = WITHDEN ? (nrm + (size_t)h * FF) : nullptr;

    const int NC = FF >> 5;   // 24
    load_chunk(0, 0);
    load_chunk(1, 1);

    for (int c = 0; c < NC; ++c) {
        if (c + 1 < NC) cp_wait<1>(); else cp_wait<0>();
        __syncthreads();
        if (c + 2 < NC) load_chunk(c + 2, (c + 2) % 3);

        const int st = c % 3;
        const uint32_t stb = sbase + (uint32_t)st * SK_STAGE;

        if (WITHDEN) {
            // den partial: 2 threads per row, 16 cols each, from A smem tiles
            int r = tid >> 1, cs = (tid & 1) * 16;
            const __nv_bfloat16* ph =
                (const __nv_bfloat16*)(sm + (size_t)st * SK_STAGE + (size_t)r * 80);
            const __nv_bfloat16* pl =
                (const __nv_bfloat16*)(sm + (size_t)st * SK_STAGE + SK_AT_B + (size_t)r * 80);
            const float* nr = nrh + (c << 5) + cs;
#pragma unroll
            for (int j = 0; j < 16; ++j) {
                float v = __bfloat162float(ph[cs + j]) + __bfloat162float(pl[cs + j]);
                den = fmaf(v, nr[j], den);
            }
        }

#pragma unroll
        for (int k16 = 0; k16 < 2; ++k16) {
            uint32_t ah[4][4], al[4][4];
#pragma unroll
            for (int mt = 0; mt < 4; ++mt) {
                uint32_t rowa = (uint32_t)(wm * 64 + mt * 16 + (lane & 15));
                uint32_t coff = (uint32_t)((k16 * 16 + ((lane >> 4) << 3)) * 2);
                ldm_x4(ah[mt], stb + 0 * SK_AT_B + rowa * 80 + coff);
                ldm_x4(al[mt], stb + 1 * SK_AT_B + rowa * 80 + coff);
            }
#pragma unroll
            for (int nt = 0; nt < 4; ++nt) {
                uint32_t rowb = (uint32_t)(k16 * 16 + (lane & 15));
                uint32_t noff = (uint32_t)((wn * 32 + nt * 8) * 2);
                uint32_t bh[2], bl[2];
                ldm_x2_t(bh, stb + 2 * SK_AT_B + 0 * SK_BT_B + rowb * 272 + noff);
                ldm_x2_t(bl, stb + 2 * SK_AT_B + 1 * SK_BT_B + rowb * 272 + noff);
#pragma unroll
                for (int mt = 0; mt < 4; ++mt) {
                    mma_bf16(acc[mt][nt], ah[mt], bh);
                    mma_bf16(acc[mt][nt], ah[mt], bl);
                    mma_bf16(acc[mt][nt], al[mt], bh);
                }
            }
        }
    }

    if (WITHDEN) {
        den += __shfl_xor_sync(0xffffffffu, den, 1);
        if (!(tid & 1))
            g_DENA[(size_t)h * S + bm + (tid >> 1)] = den + EPSV;
    }

    const int r0 = bm + wm * 64;
    const int c0 = wn * 32;
    const int rl = lane >> 2;
    const int cl = (lane & 3) * 2;
#pragma unroll
    for (int mt = 0; mt < 4; ++mt)
#pragma unroll
        for (int nt = 0; nt < 4; ++nt) {
            int col = c0 + nt * 8 + cl;
#pragma unroll
            for (int half = 0; half < 2; ++half) {
                int row = r0 + mt * 16 + rl + half * 8;
                *(float2*)(C + (size_t)row * DD + col) =
                    make_float2(acc[mt][nt][2 * half], acc[mt][nt][2 * half + 1]);
            }
        }
}

// ======================================================================
// Delta GEMM (bf16-split, split-K=4), 3-stage pipeline:
// DELTA[part][h][f,d] = sum_{s in part} MK[h/4][s,f] * WMV[h][s,d]
// ======================================================================
#define DL_T_B 8704                   // 32 x 272B
#define DL_STAGE (4 * DL_T_B)         // 34816
#define DL_SMEM  (3 * DL_STAGE)       // 104448

__global__ __launch_bounds__(256, 1) void gemm_delta_mma()
{
    extern __shared__ char sm[];
    const int tid  = threadIdx.x;
    const int lane = tid & 31;
    const int warp = tid >> 5;
    const int wm = warp >> 2;
    const int wn = warp & 3;
    const int h    = blockIdx.z;
    const int part = blockIdx.y;
    const int f0   = blockIdx.x * 128;
    const uint32_t sbase = smem_u32(sm);

    const __nv_bfloat16* Ah = g_MKH + (size_t)(h >> 2) * S * FF;
    const __nv_bfloat16* Al = g_MKL + (size_t)(h >> 2) * S * FF;
    const __nv_bfloat16* Bh = g_WMVH + (size_t)h * S * DD;
    const __nv_bfloat16* Bl = g_WMVL + (size_t)h * S * DD;

    const int kbase = part * (S / 4);

    auto load_chunk = [&](int c, int st) {
        const int k0 = kbase + (c << 5);
        const uint32_t stb = sbase + (uint32_t)st * DL_STAGE;
        const __nv_bfloat16* srcs[4] = {Ah, Al, Bh, Bl};
#pragma unroll
        for (int tile = 0; tile < 4; ++tile) {
            const bool isA = tile < 2;
#pragma unroll
            for (int rep = 0; rep < 2; ++rep) {
                int i = tid + rep * 256;
                int r = i >> 4, cc = i & 15;
                const __nv_bfloat16* src = isA
                    ? srcs[tile] + (size_t)(k0 + r) * FF + f0 + cc * 8
                    : srcs[tile] + (size_t)(k0 + r) * DD + cc * 8;
                cp_async16(stb + (uint32_t)tile * DL_T_B + r * 272 + cc * 16, src);
            }
        }
        cp_commit();
    };

    float acc[4][4][4];
#pragma unroll
    for (int mt = 0; mt < 4; ++mt)
#pragma unroll
        for (int nt = 0; nt < 4; ++nt)
#pragma unroll
            for (int r = 0; r < 4; ++r) acc[mt][nt][r] = 0.f;

    const int NC = (S / 4) >> 5;   // 32
    load_chunk(0, 0);
    load_chunk(1, 1);

    for (int c = 0; c < NC; ++c) {
        if (c + 1 < NC) cp_wait<1>(); else cp_wait<0>();
        __syncthreads();
        if (c + 2 < NC) load_chunk(c + 2, (c + 2) % 3);

        const uint32_t stb = sbase + (uint32_t)(c % 3) * DL_STAGE;
#pragma unroll
        for (int k16 = 0; k16 < 2; ++k16) {
            uint32_t ah[4][4], al[4][4];
            uint32_t rowa = (uint32_t)(k16 * 16 + (lane & 7) + ((lane >> 4) << 3));
#pragma unroll
            for (int mt = 0; mt < 4; ++mt) {
                uint32_t cola = (uint32_t)((wm * 64 + mt * 16 + (((lane >> 3) & 1) << 3)) * 2);
                ldm_x4_t(ah[mt], stb + 0 * DL_T_B + rowa * 272 + cola);
                ldm_x4_t(al[mt], stb + 1 * DL_T_B + rowa * 272 + cola);
            }
#pragma unroll
            for (int nt = 0; nt < 4; ++nt) {
                uint32_t rowb = (uint32_t)(k16 * 16 + (lane & 15));
                uint32_t noff = (uint32_t)((wn * 32 + nt * 8) * 2);
                uint32_t bh[2], bl[2];
                ldm_x2_t(bh, stb + 2 * DL_T_B + rowb * 272 + noff);
                ldm_x2_t(bl, stb + 3 * DL_T_B + rowb * 272 + noff);
#pragma unroll
                for (int mt = 0; mt < 4; ++mt) {
                    mma_bf16(acc[mt][nt], ah[mt], bh);
                    mma_bf16(acc[mt][nt], ah[mt], bl);
                    mma_bf16(acc[mt][nt], al[mt], bh);
                }
            }
        }
    }

    float* Cp = g_DELTA[part] + (size_t)h * FF * DD;
    const int r0 = f0 + wm * 64;
    const int c0 = wn * 32;
    const int rl = lane >> 2;
    const int cl = (lane & 3) * 2;
#pragma unroll
    for (int mt = 0; mt < 4; ++mt)
#pragma unroll
        for (int nt = 0; nt < 4; ++nt) {
            int col = c0 + nt * 8 + cl;
#pragma unroll
            for (int half = 0; half < 2; ++half) {
                int row = r0 + mt * 16 + rl + half * 8;
                *(float2*)(Cp + (size_t)row * DD + col) =
                    make_float2(acc[mt][nt][2 * half], acc[mt][nt][2 * half + 1]);
            }
        }
}

// ======================================================================
// dpfp + L2-normalize, emits bf16 hi/lo. K variant fuses denom/coef.
// ======================================================================
template <bool WITHDEN>
__global__ __launch_bounds__(256) void dpfp_kernel(
    const float* __restrict__ X,
    __nv_bfloat16* __restrict__ outh, __nv_bfloat16* __restrict__ outl,
    const float* __restrict__ normv)
{
    const int s  = blockIdx.x;
    const int hh = blockIdx.y;
    const int nh = gridDim.y;
    const int t  = threadIdx.x;
    __shared__ float y[256];
    __shared__ float red[5][8];

    const float* x = X + ((size_t)s * nh + hh) * 128;
    float xv = (t < 128) ? x[t] : -x[t - 128];
    y[t] = fmaxf(xv, 0.f);
    __syncthreads();

    float yi = y[t];
    float m0 = yi * y[(t - 1) & 255];
    float m1 = yi * y[(t - 2) & 255];
    float m2 = yi * y[(t - 3) & 255];
    float ss = m0 * m0 + m1 * m1 + m2 * m2;

    float dd[4];
    if (WITHDEN) {
#pragma unroll
        for (int g = 0; g < 4; g++) {
            const float* nr = normv + (size_t)(4 * hh + g) * FF;
            dd[g] = m0 * nr[t] + m1 * nr[256 + t] + m2 * nr[512 + t];
        }
    }

    const int lane = t & 31, w = t >> 5;
    float r0 = warp_sum(ss);
    if (lane == 0) red[0][w] = r0;
    if (WITHDEN) {
#pragma unroll
        for (int g = 0; g < 4; g++) {
            float rg = warp_sum(dd[g]);
            if (lane == 0) red[1 + g][w] = rg;
        }
    }
    __syncthreads();

    float ssT = 0.f;
#pragma unroll
    for (int w2 = 0; w2 < 8; w2++) ssT += red[0][w2];
    float nrm = sqrtf(ssT);
    float inv = 1.f / fmaxf(nrm, 1e-12f);

    size_t base = ((size_t)hh * S + s) * FF;
    split_write(m0 * inv, outh, outl, base + t);
    split_write(m1 * inv, outh, outl, base + 256 + t);
    split_write(m2 * inv, outh, outl, base + 512 + t);

    if (WITHDEN && t < 4) {
        float dT = 0.f;
#pragma unroll
        for (int w2 = 0; w2 < 8; w2++) dT += red[1 + t][w2];
        float den  = dT * inv + EPSV;
        float mksq = ssT * inv * inv;
        float coef = 1.f - den / mksq;
        coef = fminf(fmaxf(coef, 0.f), 1.f);
        int h = 4 * hh + t;
        g_DEN[h * S + s]  = den;
        g_COEF[h * S + s] = coef;
    }
}

// weighted_mv = (v - num/denom) * mb -> bf16 hi/lo
__global__ void wmv_kernel()
{
    size_t idx = (size_t)blockIdx.x * 256 + threadIdx.x;
    int h = (int)(idx >> 19);
    size_t r = idx & ((1u << 19) - 1);
    int s  = (int)(r >> 7);
    int d0 = (int)(r & 127);
    float den  = g_DEN[h * S + s];
    float prev = g_NUM[idx] / den;
    float v  = g_V[(size_t)s * 512 + (size_t)(h >> 2) * 128 + d0];
    float mb = g_MB[(size_t)s * HID + (size_t)h * 128 + d0];
    split_write((v - prev) * mb, g_WMVH, g_WMVL, idx);
}

// new_norm[h][f] = norm[h][f] + sum_s coef[h][s]*MK[h/4][s][f]   (MK = hi+lo)
__global__ __launch_bounds__(256) void delta_norm_kernel(
    const float* __restrict__ normv, float* __restrict__ out_norm)
{
    const int kv = blockIdx.y;
    const int f0 = blockIdx.x * 64;
    const int t  = threadIdx.x;
    const int fl = t & 63, sl = t >> 6;

    float acc[4] = {0.f, 0.f, 0.f, 0.f};
    const __nv_bfloat16* mh = g_MKH + (size_t)kv * S * FF + f0 + fl;
    const __nv_bfloat16* ml = g_MKL + (size_t)kv * S * FF + f0 + fl;
    for (int s = sl; s < S; s += 4) {
        float v = __bfloat162float(mh[(size_t)s * FF]) + __bfloat162float(ml[(size_t)s * FF]);
#pragma unroll
        for (int g = 0; g < 4; g++)
            acc[g] = fmaf(g_COEF[(4 * kv + g) * S + s], v, acc[g]);
    }
    __shared__ float smr[4][4][64];
#pragma unroll
    for (int g = 0; g < 4; g++) smr[sl][g][fl] = acc[g];
    __syncthreads();
    if (t < 64) {
#pragma unroll
        for (int g = 0; g < 4; g++) {
            float sum = smr[0][g][t] + smr[1][g][t] + smr[2][g][t] + smr[3][g][t];
            int h = 4 * kv + g;
            out_norm[(size_t)h * FF + f0 + t] = normv[(size_t)h * FF + f0 + t] + sum;
        }
    }
}

// new_memory = memory + sum partials; also emit hi/lo bf16
__global__ void add_delta_kernel(const float* __restrict__ memory,
                                 float* __restrict__ out_mem)
{
    size_t idx = (size_t)blockIdx.x * 256 + threadIdx.x;
    float v = memory[idx] + g_DELTA[0][idx] + g_DELTA[1][idx]
            + g_DELTA[2][idx] + g_DELTA[3][idx];
    out_mem[idx] = v;
    split_write(v, g_NMemH, g_NMemL, idx);
}

__global__ void final_kernel(const float* __restrict__ X, float* __restrict__ out)
{
    size_t idx = (size_t)blockIdx.x * 256 + threadIdx.x;
    int s  = (int)(idx >> 11);
    int c  = (int)(idx & 2047);
    int h  = c >> 7;
    int d0 = c & 127;
    float numa = g_NUM[((size_t)h * S + s) * DD + d0];
    float mh = numa / g_DENA[h * S + s];
    out[idx] = X[idx] + g_G[idx] * mh;
}

// ======================================================================
// Launch
// ======================================================================
extern "C" void kernel_launch(void* const* d_in, const int* in_sizes, int n_in,
                              void* d_out, int out_size)
{
    const float* X    = (const float*)d_in[0];
    const float* Wq   = (const float*)d_in[1];
    const float* bq   = (const float*)d_in[2];
    const float* Wk   = (const float*)d_in[3];
    const float* bk   = (const float*)d_in[4];
    const float* Wv   = (const float*)d_in[5];
    const float* bv   = (const float*)d_in[6];
    const float* Wg   = (const float*)d_in[7];
    const float* bg   = (const float*)d_in[8];
    const float* Wmb  = (const float*)d_in[9];
    const float* bmb  = (const float*)d_in[10];
    const float* memv = (const float*)d_in[11];
    const float* normv= (const float*)d_in[12];

    float* out      = (float*)d_out;
    float* out_mem  = out + OUT_ELEMS;
    float* out_norm = out_mem + MEM_ELEMS;

    float *pK, *pV, *pQ, *pMB, *pG, *pNUM;
    cudaGetSymbolAddress((void**)&pK,  g_K);
    cudaGetSymbolAddress((void**)&pV,  g_V);
    cudaGetSymbolAddress((void**)&pQ,  g_Q);
    cudaGetSymbolAddress((void**)&pMB, g_MB);
    cudaGetSymbolAddress((void**)&pG,  g_G);
    cudaGetSymbolAddress((void**)&pNUM, g_NUM);

    __nv_bfloat16 *xh, *xl, *wqh, *wql, *wmh, *wml, *wgh, *wgl, *wkh, *wkl, *wvh, *wvl;
    __nv_bfloat16 *mkh, *mkl, *mqh, *mql, *memh, *meml, *nmh, *nml;
    cudaGetSymbolAddress((void**)&xh,  g_XH);  cudaGetSymbolAddress((void**)&xl,  g_XL);
    cudaGetSymbolAddress((void**)&wqh, g_WqH); cudaGetSymbolAddress((void**)&wql, g_WqL);
    cudaGetSymbolAddress((void**)&wmh, g_WmH); cudaGetSymbolAddress((void**)&wml, g_WmL);
    cudaGetSymbolAddress((void**)&wgh, g_WgH); cudaGetSymbolAddress((void**)&wgl, g_WgL);
    cudaGetSymbolAddress((void**)&wkh, g_WkH); cudaGetSymbolAddress((void**)&wkl, g_WkL);
    cudaGetSymbolAddress((void**)&wvh, g_WvH); cudaGetSymbolAddress((void**)&wvl, g_WvL);
    cudaGetSymbolAddress((void**)&mkh, g_MKH); cudaGetSymbolAddress((void**)&mkl, g_MKL);
    cudaGetSymbolAddress((void**)&mqh, g_MQH); cudaGetSymbolAddress((void**)&mql, g_MQL);
    cudaGetSymbolAddress((void**)&memh, g_MemH); cudaGetSymbolAddress((void**)&meml, g_MemL);
    cudaGetSymbolAddress((void**)&nmh, g_NMemH); cudaGetSymbolAddress((void**)&nml, g_NMemL);

    cudaFuncSetAttribute(gemm_mma<0,256>, cudaFuncAttributeMaxDynamicSharedMemorySize, PJ_SMEM_256);
    cudaFuncSetAttribute(gemm_mma<1,256>, cudaFuncAttributeMaxDynamicSharedMemorySize, PJ_SMEM_256);
    cudaFuncSetAttribute(gemm_mma<0,128>, cudaFuncAttributeMaxDynamicSharedMemorySize, PJ_SMEM_128);
    cudaFuncSetAttribute(gemm_skinny_mma<0>, cudaFuncAttributeMaxDynamicSharedMemorySize, SK_SMEM);
    cudaFuncSetAttribute(gemm_skinny_mma<1>, cudaFuncAttributeMaxDynamicSharedMemorySize, SK_SMEM);
    cudaFuncSetAttribute(gemm_delta_mma, cudaFuncAttributeMaxDynamicSharedMemorySize, DL_SMEM);

    dim3 blk(256);

    // 0) fp32 -> bf16 hi/lo splits
    cvt_split<<<(S * HID / 4 + 255) / 256, blk>>>(X,   xh,  xl,  S * HID / 4);
    cvt_split<<<(HID * HID / 4 + 255) / 256, blk>>>(Wq,  wqh, wql, HID * HID / 4);
    cvt_split<<<(HID * HID / 4 + 255) / 256, blk>>>(Wmb, wmh, wml, HID * HID / 4);
    cvt_split<<<(HID * HID / 4 + 255) / 256, blk>>>(Wg,  wgh, wgl, HID * HID / 4);
    cvt_split<<<(512 * HID / 4 + 255) / 256, blk>>>(Wk,  wkh, wkl, 512 * HID / 4);
    cvt_split<<<(512 * HID / 4 + 255) / 256, blk>>>(Wv,  wvh, wvl, 512 * HID / 4);
    cvt_split<<<(MEM_ELEMS / 4 + 255) / 256, blk>>>(memv, memh, meml, MEM_ELEMS / 4);

    // 1) Projections on tensor cores (big: 128x256 tiles; K/V: 128x128)
    gemm_mma<0,256><<<dim3(HID / 256, S / 128), blk, PJ_SMEM_256>>>(xh, xl, wqh, wql, bq,  pQ,  HID, HID);
    gemm_mma<0,128><<<dim3(512 / 128, S / 128), blk, PJ_SMEM_128>>>(xh, xl, wkh, wkl, bk,  pK,  512, HID);
    gemm_mma<0,128><<<dim3(512 / 128, S / 128), blk, PJ_SMEM_128>>>(xh, xl, wvh, wvl, bv,  pV,  512, HID);
    gemm_mma<1,256><<<dim3(HID / 256, S / 128), blk, PJ_SMEM_256>>>(xh, xl, wmh, wml, bmb, pMB, HID, HID);
    gemm_mma<1,256><<<dim3(HID / 256, S / 128), blk, PJ_SMEM_256>>>(xh, xl, wgh, wgl, bg,  pG,  HID, HID);

    // 2) dpfp + normalize (bf16 hi/lo outputs)
    dpfp_kernel<true ><<<dim3(S, NKV), blk>>>(pK, mkh, mkl, normv);
    dpfp_kernel<false><<<dim3(S, NH ), blk>>>(pQ, mqh, mql, nullptr);

    // 3) num = ext_mk @ memory (tensor cores)
    gemm_skinny_mma<0><<<dim3(S / 128, NH), blk, SK_SMEM>>>(mkh, mkl, 4, memh, meml, pNUM, nullptr);

    // 4) weighted_mv (bf16 hi/lo out)
    wmv_kernel<<<(NH * S * DD) / 256, blk>>>();

    // 5) delta_memory (tensor cores, split-K=4), delta_norm, add
    gemm_delta_mma<<<dim3(FF / 128, 4, NH), blk, DL_SMEM>>>();
    delta_norm_kernel<<<dim3(FF / 64, NKV), blk>>>(normv, out_norm);
    add_delta_kernel<<<MEM_ELEMS / 256, blk>>>(memv, out_mem);

    // 6) associate: num_a GEMM with fused den_a, then output
    gemm_skinny_mma<1><<<dim3(S / 128, NH), blk, SK_SMEM>>>(mqh, mql, 1, nmh, nml, pNUM, out_norm);
    final_kernel<<<OUT_ELEMS / 256, blk>>>(X, out);
}

// round 11
// speedup vs baseline: 2.3431x; 1.0080x over previous
#include <cuda_runtime.h>
#include <cuda_bf16.h>
#include <math.h>
#include <stdint.h>

// ---------------- Problem constants ----------------
#define S      4096
#define HID    2048
#define NH     16
#define NKV    4
#define DD     128
#define FF     768
#define EPSV   1e-8f

#define OUT_ELEMS    (S * HID)
#define MEM_ELEMS    (NH * FF * DD)

// ---------------- Scratch (device globals; no allocation allowed) ----------------
__device__ __align__(16) float g_K  [S * 512];
__device__ __align__(16) float g_V  [S * 512];
__device__ __align__(16) float g_Q  [S * HID];
__device__ __align__(16) float g_MB [S * HID];
__device__ __align__(16) float g_G  [S * HID];
__device__ __align__(16) float g_NUM[(size_t)NH * S * DD];
__device__ __align__(16) float g_DELTA[4][(size_t)NH * FF * DD];
__device__ float g_DEN [NH * S];
__device__ float g_COEF[NH * S];
__device__ float g_DENA[NH * S];

// bf16 split operands
__device__ __align__(16) __nv_bfloat16 g_XH [S * HID];
__device__ __align__(16) __nv_bfloat16 g_XL [S * HID];
__device__ __align__(16) __nv_bfloat16 g_WqH[HID * HID], g_WqL[HID * HID];
__device__ __align__(16) __nv_bfloat16 g_WmH[HID * HID], g_WmL[HID * HID];
__device__ __align__(16) __nv_bfloat16 g_WgH[HID * HID], g_WgL[HID * HID];
__device__ __align__(16) __nv_bfloat16 g_WkH[512 * HID], g_WkL[512 * HID];
__device__ __align__(16) __nv_bfloat16 g_WvH[512 * HID], g_WvL[512 * HID];
__device__ __align__(16) __nv_bfloat16 g_MKH[(size_t)NKV * S * FF], g_MKL[(size_t)NKV * S * FF];
__device__ __align__(16) __nv_bfloat16 g_MQH[(size_t)NH * S * FF], g_MQL[(size_t)NH * S * FF];
__device__ __align__(16) __nv_bfloat16 g_MemH[MEM_ELEMS],  g_MemL[MEM_ELEMS];
__device__ __align__(16) __nv_bfloat16 g_NMemH[MEM_ELEMS], g_NMemL[MEM_ELEMS];
__device__ __align__(16) __nv_bfloat16 g_WMVH[(size_t)NH * S * DD], g_WMVL[(size_t)NH * S * DD];

// ---------------- helpers ----------------
__device__ __forceinline__ float warp_sum(float v) {
#pragma unroll
    for (int o = 16; o > 0; o >>= 1) v += __shfl_down_sync(0xffffffffu, v, o);
    return v;
}
__device__ __forceinline__ uint32_t smem_u32(const void* p) {
    uint32_t a;
    asm("{ .reg .u64 t; cvta.to.shared.u64 t, %1; cvt.u32.u64 %0, t; }"
        : "=r"(a) : "l"(p));
    return a;
}
__device__ __forceinline__ void cp_async16(uint32_t sa, const void* g) {
    asm volatile("cp.async.cg.shared.global [%0], [%1], 16;" :: "r"(sa), "l"(g) : "memory");
}
__device__ __forceinline__ void cp_commit() {
    asm volatile("cp.async.commit_group;" ::: "memory");
}
template<int N> __device__ __forceinline__ void cp_wait() {
    asm volatile("cp.async.wait_group %0;" :: "n"(N) : "memory");
}
__device__ __forceinline__ void ldm_x4(uint32_t* r, uint32_t addr) {
    asm volatile("ldmatrix.sync.aligned.m8n8.x4.shared.b16 {%0,%1,%2,%3}, [%4];"
                 : "=r"(r[0]), "=r"(r[1]), "=r"(r[2]), "=r"(r[3]) : "r"(addr));
}
__device__ __forceinline__ void ldm_x2(uint32_t* r, uint32_t addr) {
    asm volatile("ldmatrix.sync.aligned.m8n8.x2.shared.b16 {%0,%1}, [%2];"
                 : "=r"(r[0]), "=r"(r[1]) : "r"(addr));
}
__device__ __forceinline__ void ldm_x4_t(uint32_t* r, uint32_t addr) {
    asm volatile("ldmatrix.sync.aligned.m8n8.x4.trans.shared.b16 {%0,%1,%2,%3}, [%4];"
                 : "=r"(r[0]), "=r"(r[1]), "=r"(r[2]), "=r"(r[3]) : "r"(addr));
}
__device__ __forceinline__ void ldm_x2_t(uint32_t* r, uint32_t addr) {
    asm volatile("ldmatrix.sync.aligned.m8n8.x2.trans.shared.b16 {%0,%1}, [%2];"
                 : "=r"(r[0]), "=r"(r[1]) : "r"(addr));
}
__device__ __forceinline__ void mma_bf16(float* c, const uint32_t* a, const uint32_t* b) {
    asm volatile(
        "mma.sync.aligned.m16n8k16.row.col.f32.bf16.bf16.f32 "
        "{%0,%1,%2,%3}, {%4,%5,%6,%7}, {%8,%9}, {%0,%1,%2,%3};"
        : "+f"(c[0]), "+f"(c[1]), "+f"(c[2]), "+f"(c[3])
        : "r"(a[0]), "r"(a[1]), "r"(a[2]), "r"(a[3]), "r"(b[0]), "r"(b[1]));
}
__device__ __forceinline__ void split_write(float v, __nv_bfloat16* hp, __nv_bfloat16* lp,
                                            size_t idx) {
    __nv_bfloat16 h = __float2bfloat16(v);
    hp[idx] = h;
    lp[idx] = __float2bfloat16(v - __bfloat162float(h));
}

// ======================================================================
// fp32 -> bf16 hi/lo split conversion (vectorized x4)
// ======================================================================
__global__ void cvt_split(const float* __restrict__ x,
                          __nv_bfloat16* __restrict__ hi,
                          __nv_bfloat16* __restrict__ lo, int n4)
{
    int i = blockIdx.x * 256 + threadIdx.x;
    if (i >= n4) return;
    float4 v = ((const float4*)x)[i];
    __nv_bfloat16 h0 = __float2bfloat16(v.x), h1 = __float2bfloat16(v.y);
    __nv_bfloat16 h2 = __float2bfloat16(v.z), h3 = __float2bfloat16(v.w);
    __nv_bfloat16 l0 = __float2bfloat16(v.x - __bfloat162float(h0));
    __nv_bfloat16 l1 = __float2bfloat16(v.y - __bfloat162float(h1));
    __nv_bfloat16 l2 = __float2bfloat16(v.z - __bfloat162float(h2));
    __nv_bfloat16 l3 = __float2bfloat16(v.w - __bfloat162float(h3));
    __nv_bfloat162* hp = (__nv_bfloat162*)hi;
    __nv_bfloat162* lp = (__nv_bfloat162*)lo;
    hp[2 * i]     = __nv_bfloat162(h0, h1);
    hp[2 * i + 1] = __nv_bfloat162(h2, h3);
    lp[2 * i]     = __nv_bfloat162(l0, l1);
    lp[2 * i + 1] = __nv_bfloat162(l2, l3);
}

// ======================================================================
// Projection GEMM (bf16-split mma.sync): C = A @ W^T + bias (opt sigmoid)
// BM=128, BN template (128 or 256), BK=32, 256 threads, 8 warps (2 x 4),
// warp tile 64 x (BN/4). 3-stage cp.async pipeline, one barrier/chunk.
// ======================================================================
#define PJ_A_T 10240                        // 128 rows * 80B

template <int ACT, int BN>
__global__ __launch_bounds__(256, 1) void gemm_mma(
    const __nv_bfloat16* __restrict__ Ahi, const __nv_bfloat16* __restrict__ Alo,
    const __nv_bfloat16* __restrict__ Bhi, const __nv_bfloat16* __restrict__ Blo,
    const float* __restrict__ bias, float* __restrict__ C, int N, int K)
{
    extern __shared__ char sm[];
    constexpr int NT   = BN / 32;           // nt iterations per warp
    constexpr int B_T  = BN * 80;           // B tile bytes per half
    constexpr int STG  = 2 * PJ_A_T + 2 * B_T;
    const int tid  = threadIdx.x;
    const int lane = tid & 31;
    const int warp = tid >> 5;
    const int wm = warp >> 2;
    const int wn = warp & 3;
    const int bm = blockIdx.y * 128;
    const int bn = blockIdx.x * BN;
    const uint32_t sbase = smem_u32(sm);

    auto load_chunk = [&](int c, int st) {
        const int k0 = c << 5;
        const uint32_t stb = sbase + (uint32_t)st * STG;
#pragma unroll
        for (int half = 0; half < 2; ++half) {
            const __nv_bfloat16* src = (half ? Alo : Ahi) + (size_t)bm * K + k0;
#pragma unroll
            for (int rep = 0; rep < 2; ++rep) {
                int i = tid + rep * 256;
                int r = i >> 2, cc = i & 3;
                cp_async16(stb + (uint32_t)half * PJ_A_T + r * 80 + cc * 16,
                           src + (size_t)r * K + cc * 8);
            }
        }
#pragma unroll
        for (int half = 0; half < 2; ++half) {
            const __nv_bfloat16* src = (half ? Blo : Bhi) + (size_t)bn * K + k0;
#pragma unroll
            for (int rep = 0; rep < BN / 64; ++rep) {
                int i = tid + rep * 256;
                int r = i >> 2, cc = i & 3;
                cp_async16(stb + 2 * PJ_A_T + (uint32_t)half * B_T + r * 80 + cc * 16,
                           src + (size_t)r * K + cc * 8);
            }
        }
        cp_commit();
    };

    float acc[4][NT][4];
#pragma unroll
    for (int mt = 0; mt < 4; ++mt)
#pragma unroll
        for (int nt = 0; nt < NT; ++nt)
#pragma unroll
            for (int r = 0; r < 4; ++r) acc[mt][nt][r] = 0.f;

    const int NC = K >> 5;
    load_chunk(0, 0);
    load_chunk(1, 1);

    for (int c = 0; c < NC; ++c) {
        if (c + 1 < NC) cp_wait<1>(); else cp_wait<0>();
        __syncthreads();
        if (c + 2 < NC) load_chunk(c + 2, (c + 2) % 3);

        const uint32_t stb = sbase + (uint32_t)(c % 3) * STG;
#pragma unroll
        for (int k16 = 0; k16 < 2; ++k16) {
            uint32_t ah[4][4], al[4][4];
#pragma unroll
            for (int mt = 0; mt < 4; ++mt) {
                uint32_t rowa = (uint32_t)(wm * 64 + mt * 16 + (lane & 15));
                uint32_t coff = (uint32_t)((k16 * 16 + ((lane >> 4) << 3)) * 2);
                ldm_x4(ah[mt], stb + 0 * PJ_A_T + rowa * 80 + coff);
                ldm_x4(al[mt], stb + 1 * PJ_A_T + rowa * 80 + coff);
            }
#pragma unroll
            for (int nt = 0; nt < NT; ++nt) {
                uint32_t rowb = (uint32_t)(wn * (BN / 4) + nt * 8 + (lane & 7));
                uint32_t coff = (uint32_t)((k16 * 16 + (((lane >> 3) & 1) << 3)) * 2);
                uint32_t bh[2], bl[2];
                ldm_x2(bh, stb + 2 * PJ_A_T + 0 * B_T + rowb * 80 + coff);
                ldm_x2(bl, stb + 2 * PJ_A_T + 1 * B_T + rowb * 80 + coff);
#pragma unroll
                for (int mt = 0; mt < 4; ++mt) {
                    mma_bf16(acc[mt][nt], ah[mt], bh);
                    mma_bf16(acc[mt][nt], ah[mt], bl);
                    mma_bf16(acc[mt][nt], al[mt], bh);
                }
            }
        }
    }

    const int r0 = bm + wm * 64;
    const int c0 = bn + wn * (BN / 4);
    const int rl = lane >> 2;
    const int cl = (lane & 3) * 2;
#pragma unroll
    for (int mt = 0; mt < 4; ++mt) {
#pragma unroll
        for (int nt = 0; nt < NT; ++nt) {
            int col = c0 + nt * 8 + cl;
            float b0 = bias[col], b1 = bias[col + 1];
#pragma unroll
            for (int half = 0; half < 2; ++half) {
                int row = r0 + mt * 16 + rl + half * 8;
                float v0 = acc[mt][nt][2 * half + 0] + b0;
                float v1 = acc[mt][nt][2 * half + 1] + b1;
                if (ACT) {
                    v0 = 1.f / (1.f + expf(-v0));
                    v1 = 1.f / (1.f + expf(-v1));
                }
                *(float2*)(C + (size_t)row * N + col) = make_float2(v0, v1);
            }
        }
    }
}

#define PJ_SMEM_128 (3 * (2 * PJ_A_T + 2 * 128 * 80))   // 122880
#define PJ_SMEM_256 (3 * (2 * PJ_A_T + 2 * 256 * 80))   // 184320

// ======================================================================
// Skinny einsum GEMM (bf16-split): per head h,
// C[h][tile,128] = A[h/adiv][M,768] @ B[h][768,128].
// 3-stage pipeline. WITHDEN: fuse den_a[s] = dot(mq[s,:], nrm[h,:]) + EPS.
// ======================================================================
#define SK_AT_B 10240                 // A tile: 128 x 80B
#define SK_BT_B 8704                  // B tile: 32 x 272B
#define SK_STAGE (2*SK_AT_B + 2*SK_BT_B)   // 37888
#define SK_SMEM  (3 * SK_STAGE)            // 113664

template <int WITHDEN>
__global__ __launch_bounds__(256, 1) void gemm_skinny_mma(
    const __nv_bfloat16* __restrict__ AH, const __nv_bfloat16* __restrict__ AL,
    int adiv,
    const __nv_bfloat16* __restrict__ BH, const __nv_bfloat16* __restrict__ BL,
    float* __restrict__ Cbase, const float* __restrict__ nrm)
{
    extern __shared__ char sm[];
    const int tid  = threadIdx.x;
    const int lane = tid & 31;
    const int warp = tid >> 5;
    const int wm = warp >> 2;
    const int wn = warp & 3;
    const int h  = blockIdx.y;
    const int bm = blockIdx.x * 128;
    const uint32_t sbase = smem_u32(sm);

    const __nv_bfloat16* Ah = AH + (size_t)(h / adiv) * S * FF;
    const __nv_bfloat16* Al = AL + (size_t)(h / adiv) * S * FF;
    const __nv_bfloat16* Bh = BH + (size_t)h * FF * DD;
    const __nv_bfloat16* Bl = BL + (size_t)h * FF * DD;
    float* C = Cbase + (size_t)h * S * DD;

    auto load_chunk = [&](int c, int st) {
        const int k0 = c << 5;
        const uint32_t stb = sbase + (uint32_t)st * SK_STAGE;
        const __nv_bfloat16* asrc[2] = {Ah, Al};
        const __nv_bfloat16* bsrc[2] = {Bh, Bl};
#pragma unroll
        for (int half = 0; half < 2; ++half) {
#pragma unroll
            for (int rep = 0; rep < 2; ++rep) {
                int i = tid + rep * 256;
                int r = i >> 2, cc = i & 3;
                cp_async16(stb + (uint32_t)half * SK_AT_B + r * 80 + cc * 16,
                           asrc[half] + (size_t)(bm + r) * FF + k0 + cc * 8);
            }
#pragma unroll
            for (int rep = 0; rep < 2; ++rep) {
                int i = tid + rep * 256;
                int r = i >> 4, cc = i & 15;
                cp_async16(stb + 2 * SK_AT_B + (uint32_t)half * SK_BT_B + r * 272 + cc * 16,
                           bsrc[half] + (size_t)(k0 + r) * DD + cc * 8);
            }
        }
        cp_commit();
    };

    float acc[4][4][4];
#pragma unroll
    for (int mt = 0; mt < 4; ++mt)
#pragma unroll
        for (int nt = 0; nt < 4; ++nt)
#pragma unroll
            for (int r = 0; r < 4; ++r) acc[mt][nt][r] = 0.f;

    float den = 0.f;
    const float* nrh = WITHDEN ? (nrm + (size_t)h * FF) : nullptr;

    const int NC = FF >> 5;   // 24
    load_chunk(0, 0);
    load_chunk(1, 1);

    for (int c = 0; c < NC; ++c) {
        if (c + 1 < NC) cp_wait<1>(); else cp_wait<0>();
        __syncthreads();
        if (c + 2 < NC) load_chunk(c + 2, (c + 2) % 3);

        const int st = c % 3;
        const uint32_t stb = sbase + (uint32_t)st * SK_STAGE;

        if (WITHDEN) {
            // den partial: 2 threads per row, 16 cols each, from A smem tiles
            int r = tid >> 1, cs = (tid & 1) * 16;
            const __nv_bfloat16* ph =
                (const __nv_bfloat16*)(sm + (size_t)st * SK_STAGE + (size_t)r * 80);
            const __nv_bfloat16* pl =
                (const __nv_bfloat16*)(sm + (size_t)st * SK_STAGE + SK_AT_B + (size_t)r * 80);
            const float* nr = nrh + (c << 5) + cs;
#pragma unroll
            for (int j = 0; j < 16; ++j) {
                float v = __bfloat162float(ph[cs + j]) + __bfloat162float(pl[cs + j]);
                den = fmaf(v, nr[j], den);
            }
        }

#pragma unroll
        for (int k16 = 0; k16 < 2; ++k16) {
            uint32_t ah[4][4], al[4][4];
#pragma unroll
            for (int mt = 0; mt < 4; ++mt) {
                uint32_t rowa = (uint32_t)(wm * 64 + mt * 16 + (lane & 15));
                uint32_t coff = (uint32_t)((k16 * 16 + ((lane >> 4) << 3)) * 2);
                ldm_x4(ah[mt], stb + 0 * SK_AT_B + rowa * 80 + coff);
                ldm_x4(al[mt], stb + 1 * SK_AT_B + rowa * 80 + coff);
            }
#pragma unroll
            for (int nt = 0; nt < 4; ++nt) {
                uint32_t rowb = (uint32_t)(k16 * 16 + (lane & 15));
                uint32_t noff = (uint32_t)((wn * 32 + nt * 8) * 2);
                uint32_t bh[2], bl[2];
                ldm_x2_t(bh, stb + 2 * SK_AT_B + 0 * SK_BT_B + rowb * 272 + noff);
                ldm_x2_t(bl, stb + 2 * SK_AT_B + 1 * SK_BT_B + rowb * 272 + noff);
#pragma unroll
                for (int mt = 0; mt < 4; ++mt) {
                    mma_bf16(acc[mt][nt], ah[mt], bh);
                    mma_bf16(acc[mt][nt], ah[mt], bl);
                    mma_bf16(acc[mt][nt], al[mt], bh);
                }
            }
        }
    }

    if (WITHDEN) {
        den += __shfl_xor_sync(0xffffffffu, den, 1);
        if (!(tid & 1))
            g_DENA[(size_t)h * S + bm + (tid >> 1)] = den + EPSV;
    }

    const int r0 = bm + wm * 64;
    const int c0 = wn * 32;
    const int rl = lane >> 2;
    const int cl = (lane & 3) * 2;
#pragma unroll
    for (int mt = 0; mt < 4; ++mt)
#pragma unroll
        for (int nt = 0; nt < 4; ++nt) {
            int col = c0 + nt * 8 + cl;
#pragma unroll
            for (int half = 0; half < 2; ++half) {
                int row = r0 + mt * 16 + rl + half * 8;
                *(float2*)(C + (size_t)row * DD + col) =
                    make_float2(acc[mt][nt][2 * half], acc[mt][nt][2 * half + 1]);
            }
        }
}

// ======================================================================
// Delta GEMM (bf16-split, split-K=4), 3-stage pipeline:
// DELTA[part][h][f,d] = sum_{s in part} MK[h/4][s,f] * WMV[h][s,d]
// ======================================================================
#define DL_T_B 8704                   // 32 x 272B
#define DL_STAGE (4 * DL_T_B)         // 34816
#define DL_SMEM  (3 * DL_STAGE)       // 104448

__global__ __launch_bounds__(256, 1) void gemm_delta_mma()
{
    extern __shared__ char sm[];
    const int tid  = threadIdx.x;
    const int lane = tid & 31;
    const int warp = tid >> 5;
    const int wm = warp >> 2;
    const int wn = warp & 3;
    const int h    = blockIdx.z;
    const int part = blockIdx.y;
    const int f0   = blockIdx.x * 128;
    const uint32_t sbase = smem_u32(sm);

    const __nv_bfloat16* Ah = g_MKH + (size_t)(h >> 2) * S * FF;
    const __nv_bfloat16* Al = g_MKL + (size_t)(h >> 2) * S * FF;
    const __nv_bfloat16* Bh = g_WMVH + (size_t)h * S * DD;
    const __nv_bfloat16* Bl = g_WMVL + (size_t)h * S * DD;

    const int kbase = part * (S / 4);

    auto load_chunk = [&](int c, int st) {
        const int k0 = kbase + (c << 5);
        const uint32_t stb = sbase + (uint32_t)st * DL_STAGE;
        const __nv_bfloat16* srcs[4] = {Ah, Al, Bh, Bl};
#pragma unroll
        for (int tile = 0; tile < 4; ++tile) {
            const bool isA = tile < 2;
#pragma unroll
            for (int rep = 0; rep < 2; ++rep) {
                int i = tid + rep * 256;
                int r = i >> 4, cc = i & 15;
                const __nv_bfloat16* src = isA
                    ? srcs[tile] + (size_t)(k0 + r) * FF + f0 + cc * 8
                    : srcs[tile] + (size_t)(k0 + r) * DD + cc * 8;
                cp_async16(stb + (uint32_t)tile * DL_T_B + r * 272 + cc * 16, src);
            }
        }
        cp_commit();
    };

    float acc[4][4][4];
#pragma unroll
    for (int mt = 0; mt < 4; ++mt)
#pragma unroll
        for (int nt = 0; nt < 4; ++nt)
#pragma unroll
            for (int r = 0; r < 4; ++r) acc[mt][nt][r] = 0.f;

    const int NC = (S / 4) >> 5;   // 32
    load_chunk(0, 0);
    load_chunk(1, 1);

    for (int c = 0; c < NC; ++c) {
        if (c + 1 < NC) cp_wait<1>(); else cp_wait<0>();
        __syncthreads();
        if (c + 2 < NC) load_chunk(c + 2, (c + 2) % 3);

        const uint32_t stb = sbase + (uint32_t)(c % 3) * DL_STAGE;
#pragma unroll
        for (int k16 = 0; k16 < 2; ++k16) {
            uint32_t ah[4][4], al[4][4];
            uint32_t rowa = (uint32_t)(k16 * 16 + (lane & 7) + ((lane >> 4) << 3));
#pragma unroll
            for (int mt = 0; mt < 4; ++mt) {
                uint32_t cola = (uint32_t)((wm * 64 + mt * 16 + (((lane >> 3) & 1) << 3)) * 2);
                ldm_x4_t(ah[mt], stb + 0 * DL_T_B + rowa * 272 + cola);
                ldm_x4_t(al[mt], stb + 1 * DL_T_B + rowa * 272 + cola);
            }
#pragma unroll
            for (int nt = 0; nt < 4; ++nt) {
                uint32_t rowb = (uint32_t)(k16 * 16 + (lane & 15));
                uint32_t noff = (uint32_t)((wn * 32 + nt * 8) * 2);
                uint32_t bh[2], bl[2];
                ldm_x2_t(bh, stb + 2 * DL_T_B + rowb * 272 + noff);
                ldm_x2_t(bl, stb + 3 * DL_T_B + rowb * 272 + noff);
#pragma unroll
                for (int mt = 0; mt < 4; ++mt) {
                    mma_bf16(acc[mt][nt], ah[mt], bh);
                    mma_bf16(acc[mt][nt], ah[mt], bl);
                    mma_bf16(acc[mt][nt], al[mt], bh);
                }
            }
        }
    }

    float* Cp = g_DELTA[part] + (size_t)h * FF * DD;
    const int r0 = f0 + wm * 64;
    const int c0 = wn * 32;
    const int rl = lane >> 2;
    const int cl = (lane & 3) * 2;
#pragma unroll
    for (int mt = 0; mt < 4; ++mt)
#pragma unroll
        for (int nt = 0; nt < 4; ++nt) {
            int col = c0 + nt * 8 + cl;
#pragma unroll
            for (int half = 0; half < 2; ++half) {
                int row = r0 + mt * 16 + rl + half * 8;
                *(float2*)(Cp + (size_t)row * DD + col) =
                    make_float2(acc[mt][nt][2 * half], acc[mt][nt][2 * half + 1]);
            }
        }
}

// ======================================================================
// dpfp + L2-normalize, emits bf16 hi/lo. K variant fuses denom/coef.
// ======================================================================
template <bool WITHDEN>
__global__ __launch_bounds__(256) void dpfp_kernel(
    const float* __restrict__ X,
    __nv_bfloat16* __restrict__ outh, __nv_bfloat16* __restrict__ outl,
    const float* __restrict__ normv)
{
    const int s  = blockIdx.x;
    const int hh = blockIdx.y;
    const int nh = gridDim.y;
    const int t  = threadIdx.x;
    __shared__ float y[256];
    __shared__ float red[5][8];

    const float* x = X + ((size_t)s * nh + hh) * 128;
    float xv = (t < 128) ? x[t] : -x[t - 128];
    y[t] = fmaxf(xv, 0.f);
    __syncthreads();

    float yi = y[t];
    float m0 = yi * y[(t - 1) & 255];
    float m1 = yi * y[(t - 2) & 255];
    float m2 = yi * y[(t - 3) & 255];
    float ss = m0 * m0 + m1 * m1 + m2 * m2;

    float dd[4];
    if (WITHDEN) {
#pragma unroll
        for (int g = 0; g < 4; g++) {
            const float* nr = normv + (size_t)(4 * hh + g) * FF;
            dd[g] = m0 * nr[t] + m1 * nr[256 + t] + m2 * nr[512 + t];
        }
    }

    const int lane = t & 31, w = t >> 5;
    float r0 = warp_sum(ss);
    if (lane == 0) red[0][w] = r0;
    if (WITHDEN) {
#pragma unroll
        for (int g = 0; g < 4; g++) {
            float rg = warp_sum(dd[g]);
            if (lane == 0) red[1 + g][w] = rg;
        }
    }
    __syncthreads();

    float ssT = 0.f;
#pragma unroll
    for (int w2 = 0; w2 < 8; w2++) ssT += red[0][w2];
    float nrm = sqrtf(ssT);
    float inv = 1.f / fmaxf(nrm, 1e-12f);

    size_t base = ((size_t)hh * S + s) * FF;
    split_write(m0 * inv, outh, outl, base + t);
    split_write(m1 * inv, outh, outl, base + 256 + t);
    split_write(m2 * inv, outh, outl, base + 512 + t);

    if (WITHDEN && t < 4) {
        float dT = 0.f;
#pragma unroll
        for (int w2 = 0; w2 < 8; w2++) dT += red[1 + t][w2];
        float den  = dT * inv + EPSV;
        float mksq = ssT * inv * inv;
        float coef = 1.f - den / mksq;
        coef = fminf(fmaxf(coef, 0.f), 1.f);
        int h = 4 * hh + t;
        g_DEN[h * S + s]  = den;
        g_COEF[h * S + s] = coef;
    }
}

// weighted_mv = (v - num/denom) * mb -> bf16 hi/lo
__global__ void wmv_kernel()
{
    size_t idx = (size_t)blockIdx.x * 256 + threadIdx.x;
    int h = (int)(idx >> 19);
    size_t r = idx & ((1u << 19) - 1);
    int s  = (int)(r >> 7);
    int d0 = (int)(r & 127);
    float den  = g_DEN[h * S + s];
    float prev = g_NUM[idx] / den;
    float v  = g_V[(size_t)s * 512 + (size_t)(h >> 2) * 128 + d0];
    float mb = g_MB[(size_t)s * HID + (size_t)h * 128 + d0];
    split_write((v - prev) * mb, g_WMVH, g_WMVL, idx);
}

// new_norm[h][f] = norm[h][f] + sum_s coef[h][s]*MK[h/4][s][f]   (MK = hi+lo)
__global__ __launch_bounds__(256) void delta_norm_kernel(
    const float* __restrict__ normv, float* __restrict__ out_norm)
{
    const int kv = blockIdx.y;
    const int f0 = blockIdx.x * 64;
    const int t  = threadIdx.x;
    const int fl = t & 63, sl = t >> 6;

    float acc[4] = {0.f, 0.f, 0.f, 0.f};
    const __nv_bfloat16* mh = g_MKH + (size_t)kv * S * FF + f0 + fl;
    const __nv_bfloat16* ml = g_MKL + (size_t)kv * S * FF + f0 + fl;
    for (int s = sl; s < S; s += 4) {
        float v = __bfloat162float(mh[(size_t)s * FF]) + __bfloat162float(ml[(size_t)s * FF]);
#pragma unroll
        for (int g = 0; g < 4; g++)
            acc[g] = fmaf(g_COEF[(4 * kv + g) * S + s], v, acc[g]);
    }
    __shared__ float smr[4][4][64];
#pragma unroll
    for (int g = 0; g < 4; g++) smr[sl][g][fl] = acc[g];
    __syncthreads();
    if (t < 64) {
#pragma unroll
        for (int g = 0; g < 4; g++) {
            float sum = smr[0][g][t] + smr[1][g][t] + smr[2][g][t] + smr[3][g][t];
            int h = 4 * kv + g;
            out_norm[(size_t)h * FF + f0 + t] = normv[(size_t)h * FF + f0 + t] + sum;
        }
    }
}

// new_memory = memory + sum partials; also emit hi/lo bf16
__global__ void add_delta_kernel(const float* __restrict__ memory,
                                 float* __restrict__ out_mem)
{
    size_t idx = (size_t)blockIdx.x * 256 + threadIdx.x;
    float v = memory[idx] + g_DELTA[0][idx] + g_DELTA[1][idx]
            + g_DELTA[2][idx] + g_DELTA[3][idx];
    out_mem[idx] = v;
    split_write(v, g_NMemH, g_NMemL, idx);
}

__global__ void final_kernel(const float* __restrict__ X, float* __restrict__ out)
{
    size_t idx = (size_t)blockIdx.x * 256 + threadIdx.x;
    int s  = (int)(idx >> 11);
    int c  = (int)(idx & 2047);
    int h  = c >> 7;
    int d0 = c & 127;
    float numa = g_NUM[((size_t)h * S + s) * DD + d0];
    float mh = numa / g_DENA[h * S + s];
    out[idx] = X[idx] + g_G[idx] * mh;
}

// ======================================================================
// Launch
// ======================================================================
extern "C" void kernel_launch(void* const* d_in, const int* in_sizes, int n_in,
                              void* d_out, int out_size)
{
    const float* X    = (const float*)d_in[0];
    const float* Wq   = (const float*)d_in[1];
    const float* bq   = (const float*)d_in[2];
    const float* Wk   = (const float*)d_in[3];
    const float* bk   = (const float*)d_in[4];
    const float* Wv   = (const float*)d_in[5];
    const float* bv   = (const float*)d_in[6];
    const float* Wg   = (const float*)d_in[7];
    const float* bg   = (const float*)d_in[8];
    const float* Wmb  = (const float*)d_in[9];
    const float* bmb  = (const float*)d_in[10];
    const float* memv = (const float*)d_in[11];
    const float* normv= (const float*)d_in[12];

    float* out      = (float*)d_out;
    float* out_mem  = out + OUT_ELEMS;
    float* out_norm = out_mem + MEM_ELEMS;

    float *pK, *pV, *pQ, *pMB, *pG, *pNUM;
    cudaGetSymbolAddress((void**)&pK,  g_K);
    cudaGetSymbolAddress((void**)&pV,  g_V);
    cudaGetSymbolAddress((void**)&pQ,  g_Q);
    cudaGetSymbolAddress((void**)&pMB, g_MB);
    cudaGetSymbolAddress((void**)&pG,  g_G);
    cudaGetSymbolAddress((void**)&pNUM, g_NUM);

    __nv_bfloat16 *xh, *xl, *wqh, *wql, *wmh, *wml, *wgh, *wgl, *wkh, *wkl, *wvh, *wvl;
    __nv_bfloat16 *mkh, *mkl, *mqh, *mql, *memh, *meml, *nmh, *nml;
    cudaGetSymbolAddress((void**)&xh,  g_XH);  cudaGetSymbolAddress((void**)&xl,  g_XL);
    cudaGetSymbolAddress((void**)&wqh, g_WqH); cudaGetSymbolAddress((void**)&wql, g_WqL);
    cudaGetSymbolAddress((void**)&wmh, g_WmH); cudaGetSymbolAddress((void**)&wml, g_WmL);
    cudaGetSymbolAddress((void**)&wgh, g_WgH); cudaGetSymbolAddress((void**)&wgl, g_WgL);
    cudaGetSymbolAddress((void**)&wkh, g_WkH); cudaGetSymbolAddress((void**)&wkl, g_WkL);
    cudaGetSymbolAddress((void**)&wvh, g_WvH); cudaGetSymbolAddress((void**)&wvl, g_WvL);
    cudaGetSymbolAddress((void**)&mkh, g_MKH); cudaGetSymbolAddress((void**)&mkl, g_MKL);
    cudaGetSymbolAddress((void**)&mqh, g_MQH); cudaGetSymbolAddress((void**)&mql, g_MQL);
    cudaGetSymbolAddress((void**)&memh, g_MemH); cudaGetSymbolAddress((void**)&meml, g_MemL);
    cudaGetSymbolAddress((void**)&nmh, g_NMemH); cudaGetSymbolAddress((void**)&nml, g_NMemL);

    cudaFuncSetAttribute(gemm_mma<0,256>, cudaFuncAttributeMaxDynamicSharedMemorySize, PJ_SMEM_256);
    cudaFuncSetAttribute(gemm_mma<1,256>, cudaFuncAttributeMaxDynamicSharedMemorySize, PJ_SMEM_256);
    cudaFuncSetAttribute(gemm_mma<0,128>, cudaFuncAttributeMaxDynamicSharedMemorySize, PJ_SMEM_128);
    cudaFuncSetAttribute(gemm_skinny_mma<0>, cudaFuncAttributeMaxDynamicSharedMemorySize, SK_SMEM);
    cudaFuncSetAttribute(gemm_skinny_mma<1>, cudaFuncAttributeMaxDynamicSharedMemorySize, SK_SMEM);
    cudaFuncSetAttribute(gemm_delta_mma, cudaFuncAttributeMaxDynamicSharedMemorySize, DL_SMEM);

    dim3 blk(256);

    // 0) fp32 -> bf16 hi/lo splits
    cvt_split<<<(S * HID / 4 + 255) / 256, blk>>>(X,   xh,  xl,  S * HID / 4);
    cvt_split<<<(HID * HID / 4 + 255) / 256, blk>>>(Wq,  wqh, wql, HID * HID / 4);
    cvt_split<<<(HID * HID / 4 + 255) / 256, blk>>>(Wmb, wmh, wml, HID * HID / 4);
    cvt_split<<<(HID * HID / 4 + 255) / 256, blk>>>(Wg,  wgh, wgl, HID * HID / 4);
    cvt_split<<<(512 * HID / 4 + 255) / 256, blk>>>(Wk,  wkh, wkl, 512 * HID / 4);
    cvt_split<<<(512 * HID / 4 + 255) / 256, blk>>>(Wv,  wvh, wvl, 512 * HID / 4);
    cvt_split<<<(MEM_ELEMS / 4 + 255) / 256, blk>>>(memv, memh, meml, MEM_ELEMS / 4);

    // 1) Projections on tensor cores (big: 128x256 tiles; K/V: 128x128)
    gemm_mma<0,256><<<dim3(HID / 256, S / 128), blk, PJ_SMEM_256>>>(xh, xl, wqh, wql, bq,  pQ,  HID, HID);
    gemm_mma<0,128><<<dim3(512 / 128, S / 128), blk, PJ_SMEM_128>>>(xh, xl, wkh, wkl, bk,  pK,  512, HID);
    gemm_mma<0,128><<<dim3(512 / 128, S / 128), blk, PJ_SMEM_128>>>(xh, xl, wvh, wvl, bv,  pV,  512, HID);
    gemm_mma<1,256><<<dim3(HID / 256, S / 128), blk, PJ_SMEM_256>>>(xh, xl, wmh, wml, bmb, pMB, HID, HID);
    gemm_mma<1,256><<<dim3(HID / 256, S / 128), blk, PJ_SMEM_256>>>(xh, xl, wgh, wgl, bg,  pG,  HID, HID);

    // 2) dpfp + normalize (bf16 hi/lo outputs)
    dpfp_kernel<true ><<<dim3(S, NKV), blk>>>(pK, mkh, mkl, normv);
    dpfp_kernel<false><<<dim3(S, NH ), blk>>>(pQ, mqh, mql, nullptr);

    // 3) num = ext_mk @ memory (tensor cores)
    gemm_skinny_mma<0><<<dim3(S / 128, NH), blk, SK_SMEM>>>(mkh, mkl, 4, memh, meml, pNUM, nullptr);

    // 4) weighted_mv (bf16 hi/lo out)
    wmv_kernel<<<(NH * S * DD) / 256, blk>>>();

    // 5) delta_memory (tensor cores, split-K=4), delta_norm, add
    gemm_delta_mma<<<dim3(FF / 128, 4, NH), blk, DL_SMEM>>>();
    delta_norm_kernel<<<dim3(FF / 64, NKV), blk>>>(normv, out_norm);
    add_delta_kernel<<<MEM_ELEMS / 256, blk>>>(memv, out_mem);

    // 6) associate: num_a GEMM with fused den_a, then output
    gemm_skinny_mma<1><<<dim3(S / 128, NH), blk, SK_SMEM>>>(mqh, mql, 1, nmh, nml, pNUM, out_norm);
    final_kernel<<<OUT_ELEMS / 256, blk>>>(X, out);
}